// round 3
// baseline (speedup 1.0000x reference)
#include <cuda_runtime.h>
#include <cuda_fp16.h>
#include <mma.h>
#include <cstddef>

using namespace nvcuda;

// ---------------------------------------------------------------------------
// Static scratch
// ---------------------------------------------------------------------------
#define NMAX 50000
#define EMAX 1600000

__device__ float  g_agg1[NMAX * 2];
__device__ __half g_h1s[(size_t)NMAX * 256];   // layer1 out, split fp16 [hi128|lo128]
__device__ float  g_C[(size_t)NMAX * 128];     // gemm out [y64|r64] fp32 (L2 & L3 reuse)
__device__ __half g_h2s[(size_t)NMAX * 128];   // h2 split [hi64|lo64]
__device__ __half g_zs[(size_t)NMAX * 128];    // z split  [hi64|lo64]
__device__ __half g_uv[(size_t)NMAX * 256];    // decoder [u128|v128] fp16

// split weights + biases
__device__ __half g_ws2[256 * 128];            // L2: K=128 -> rows [hi128|lo128], OUT=128
__device__ __half g_ws3[128 * 128];            // L3: K=64,  OUT=128
__device__ __half g_wsd[128 * 256];            // dec: K=64, OUT=256
__device__ float  g_bias2[128];
__device__ float  g_bias3[128];
__device__ float  g_biasd[256];

// CSR scratch
__device__ int  g_cnt[NMAX];
__device__ int  g_roff[NMAX + 1];
__device__ int  g_cursor[NMAX];
__device__ int2 g_csr[EMAX];

// ---------------------------------------------------------------------------
// CSR build
// ---------------------------------------------------------------------------
__global__ void hist_kernel(const int* __restrict__ dst, int* __restrict__ cnt, int E) {
    int e = blockIdx.x * blockDim.x + threadIdx.x;
    if (e >= E) return;
    atomicAdd(&cnt[dst[e]], 1);
}

__global__ void scan_counts(const int* __restrict__ cnt, int* __restrict__ roff,
                            int* __restrict__ cursor, int N) {
    __shared__ int wsum[32];
    __shared__ int carry;
    int tid = threadIdx.x;
    int lane = tid & 31, wid = tid >> 5;
    if (tid == 0) carry = 0;
    __syncthreads();
    int nchunk = (N + 1023) >> 10;
    for (int c = 0; c < nchunk; c++) {
        int i = (c << 10) + tid;
        int v = (i < N) ? cnt[i] : 0;
        int s = v;
#pragma unroll
        for (int o = 1; o < 32; o <<= 1) {
            int t = __shfl_up_sync(0xFFFFFFFFu, s, o);
            if (lane >= o) s += t;
        }
        if (lane == 31) wsum[wid] = s;
        __syncthreads();
        if (wid == 0) {
            int ws = wsum[lane];
#pragma unroll
            for (int o = 1; o < 32; o <<= 1) {
                int t = __shfl_up_sync(0xFFFFFFFFu, ws, o);
                if (lane >= o) ws += t;
            }
            wsum[lane] = ws;
        }
        __syncthreads();
        int base = carry + (wid > 0 ? wsum[wid - 1] : 0);
        int excl = base + s - v;
        if (i < N) { roff[i] = excl; cursor[i] = excl; }
        __syncthreads();
        if (tid == 1023) carry += wsum[31];
        __syncthreads();
    }
    if (tid == 0) roff[N] = carry;
}

__global__ void fill_kernel(const int* __restrict__ src, const int* __restrict__ dst,
                            const float* __restrict__ ew, int* __restrict__ cursor,
                            int2* __restrict__ csr, int E) {
    int e = blockIdx.x * blockDim.x + threadIdx.x;
    if (e >= E) return;
    int d = dst[e];
    int p = atomicAdd(&cursor[d], 1);
    csr[p] = make_int2(src[e], __float_as_int(ew[e]));
}

// ---------------------------------------------------------------------------
// Weight split prep: out [2K x OUT] fp16; col j<OUTa from Wa else Wb.
// ---------------------------------------------------------------------------
__global__ void prep_split(const float* __restrict__ Wa, const float* __restrict__ Wb,
                           __half* __restrict__ out, int K, int OUT, int OUTa, int OUTb) {
    int idx = blockIdx.x * blockDim.x + threadIdx.x;
    if (idx >= K * OUT) return;
    int k = idx / OUT, j = idx - k * OUT;
    float v = (j < OUTa) ? Wa[k * OUTa + j] : Wb[k * OUTb + (j - OUTa)];
    __half hi = __float2half_rn(v);
    __half lo = __float2half_rn(v - __half2float(hi));
    out[(size_t)k * OUT + j] = hi;
    out[(size_t)(K + k) * OUT + j] = lo;
}

__global__ void prep_bias(const float* __restrict__ src, float* __restrict__ dst,
                          int off, int len, int total) {
    int i = blockIdx.x * blockDim.x + threadIdx.x;
    if (i >= total) return;
    dst[i] = (i >= off && i < off + len) ? src[i - off] : 0.f;
}

// ---------------------------------------------------------------------------
// Layer 1 gather: 4 lanes/node, quad shuffle reduce (2 feats)
// ---------------------------------------------------------------------------
__global__ void gather_l1(const int2* __restrict__ csr, const int* __restrict__ roff,
                          const float* __restrict__ x, float* __restrict__ agg1, int N) {
    int tid = blockIdx.x * blockDim.x + threadIdx.x;
    int n = tid >> 2;
    int l = tid & 3;
    bool valid = (n < N);
    int nc = valid ? n : (N - 1);
    int beg = __ldg(roff + nc), end = __ldg(roff + nc + 1);
    float a0 = 0.f, a1 = 0.f;
    for (int i = beg + l; i < end; i += 4) {
        int2 p = __ldg(csr + i);
        float w = __int_as_float(p.y);
        float2 xv = __ldg((const float2*)(x + 2 * (size_t)p.x));
        a0 += w * xv.x;
        a1 += w * xv.y;
    }
#pragma unroll
    for (int o = 1; o < 4; o <<= 1) {
        a0 += __shfl_xor_sync(0xFFFFFFFFu, a0, o);
        a1 += __shfl_xor_sync(0xFFFFFFFFu, a1, o);
    }
    if (valid && l == 0) ((float2*)agg1)[n] = make_float2(a0, a1);
}

// ---------------------------------------------------------------------------
// Layer 1 combine -> split fp16: h1s[n][f]=hi, h1s[n][128+f]=lo   (2 -> 128)
// Thread handles 2 feats (half2 stores).
// ---------------------------------------------------------------------------
__global__ void layer1_kernel(const float* __restrict__ x,
                              const float* __restrict__ agg1,
                              const float* __restrict__ W1_rel,
                              const float* __restrict__ W1_root,
                              const float* __restrict__ b1,
                              __half* __restrict__ h1s, int N) {
    int tid = blockIdx.x * blockDim.x + threadIdx.x;
    if (tid >= N * 64) return;
    int n = tid >> 6;
    int f = (tid & 63) << 1;
    float a0 = agg1[2 * n], a1 = agg1[2 * n + 1];
    float x0 = x[2 * n], x1 = x[2 * n + 1];
    float v0 = a0 * W1_rel[f] + a1 * W1_rel[128 + f]
             + x0 * W1_root[f] + x1 * W1_root[128 + f] + b1[f];
    float v1 = a0 * W1_rel[f + 1] + a1 * W1_rel[129 + f]
             + x0 * W1_root[f + 1] + x1 * W1_root[129 + f] + b1[f + 1];
    v0 = fmaxf(v0, 0.f);
    v1 = fmaxf(v1, 0.f);
    __half h0 = __float2half_rn(v0), h1 = __float2half_rn(v1);
    __half l0 = __float2half_rn(v0 - __half2float(h0));
    __half l1 = __float2half_rn(v1 - __half2float(h1));
    *(__half2*)(h1s + (size_t)n * 256 + f) = __halves2half2(h0, h1);
    *(__half2*)(h1s + (size_t)n * 256 + 128 + f) = __halves2half2(l0, l1);
}

// ---------------------------------------------------------------------------
// Split-fp16 tensor-core GEMM:
//   C[N x OUT] = (H_hi+H_lo)[N x K] @ (W_hi+W_lo)[K x OUT] + bias  (3-term)
// Hs: [N x 2K] fp16 (hi cols [0,K), lo cols [K,2K))
// Ws: [2K x OUT] fp16 (hi rows [0,K), lo rows [K,2K))
// Segments: (hi,Whi), (lo,Whi), (hi,Wlo)
// ---------------------------------------------------------------------------
template <int K, int OUT, typename TOut>
__global__ void gemm_wmma(const __half* __restrict__ Hs,
                          const __half* __restrict__ Ws,
                          const float* __restrict__ bias,
                          TOut* __restrict__ C, int N) {
    constexpr int NKT = K / 16;
    __shared__ __align__(16) __half sh_h[64 * 16];
    __shared__ __align__(16) __half sh_w[16 * 64];
    __shared__ __align__(16) float  sh_c[64 * 64];

    int m0 = blockIdx.x * 64;
    int n0 = blockIdx.y * 64;
    int t = threadIdx.x;         // 128 threads
    int warp = t >> 5;
    int wm = (warp & 1) * 32, wn = (warp >> 1) * 32;

    wmma::fragment<wmma::accumulator, 16, 16, 16, float> acc[2][2];
#pragma unroll
    for (int i = 0; i < 2; i++)
#pragma unroll
        for (int j = 0; j < 2; j++) wmma::fill_fragment(acc[i][j], 0.f);

    for (int t3 = 0; t3 < 3 * NKT; t3++) {
        int seg = t3 / NKT, kt = t3 - seg * NKT;
        int hc = (seg == 1 ? K : 0) + kt * 16;
        int wr = (seg == 2 ? K : 0) + kt * 16;
        // H tile 64x16: each thread loads 8 halves (16B)
        {
            int row = t >> 1;
            int col8 = (t & 1) * 8;
            int n = m0 + row;
            uint4 v = make_uint4(0, 0, 0, 0);
            if (n < N) v = *(const uint4*)(Hs + (size_t)n * (2 * K) + hc + col8);
            *(uint4*)&sh_h[row * 16 + col8] = v;
        }
        // W tile 16x64
        {
            int row = t >> 3;
            int col8 = (t & 7) * 8;
            *(uint4*)&sh_w[row * 64 + col8] =
                *(const uint4*)(Ws + (size_t)(wr + row) * OUT + n0 + col8);
        }
        __syncthreads();
        wmma::fragment<wmma::matrix_a, 16, 16, 16, __half, wmma::row_major> a0, a1;
        wmma::fragment<wmma::matrix_b, 16, 16, 16, __half, wmma::row_major> b0, b1;
        wmma::load_matrix_sync(a0, &sh_h[(wm + 0) * 16], 16);
        wmma::load_matrix_sync(a1, &sh_h[(wm + 16) * 16], 16);
        wmma::load_matrix_sync(b0, &sh_w[wn + 0], 64);
        wmma::load_matrix_sync(b1, &sh_w[wn + 16], 64);
        wmma::mma_sync(acc[0][0], a0, b0, acc[0][0]);
        wmma::mma_sync(acc[0][1], a0, b1, acc[0][1]);
        wmma::mma_sync(acc[1][0], a1, b0, acc[1][0]);
        wmma::mma_sync(acc[1][1], a1, b1, acc[1][1]);
        __syncthreads();
    }
#pragma unroll
    for (int i = 0; i < 2; i++)
#pragma unroll
        for (int j = 0; j < 2; j++)
            wmma::store_matrix_sync(&sh_c[(wm + i * 16) * 64 + wn + j * 16],
                                    acc[i][j], 64, wmma::mem_row_major);
    __syncthreads();

    for (int idx = t; idx < 64 * 64; idx += 128) {
        int j = idx >> 6, c = idx & 63;
        int n = m0 + j;
        if (n < N) {
            float v = sh_c[idx] + __ldg(bias + n0 + c);
            C[(size_t)n * OUT + n0 + c] = (TOut)v;
        }
    }
}

// ---------------------------------------------------------------------------
// Fused gather + residual + act. C holds [y64|r64] rows of 128 fp32.
// Writes fp32 out (optional) and/or split fp16 (optional). 8 lanes/node.
// ---------------------------------------------------------------------------
__global__ void gather64(const int2* __restrict__ csr, const int* __restrict__ roff,
                         const float* __restrict__ C, float* __restrict__ out32,
                         __half* __restrict__ split, int N, int do_relu) {
    int node = blockIdx.x * 32 + (threadIdx.x >> 3);
    int c = threadIdx.x & 7;
    if (node >= N) return;
    int beg = __ldg(roff + node);
    int end = __ldg(roff + node + 1);
    float4 a0 = make_float4(0, 0, 0, 0);
    float4 a1 = make_float4(0, 0, 0, 0);
    int i = beg;
    for (; i + 2 <= end; i += 2) {
        int2 p0 = __ldg(csr + i);
        int2 p1 = __ldg(csr + i + 1);
        const float4* r0 = (const float4*)(C + (size_t)p0.x * 128);
        const float4* r1 = (const float4*)(C + (size_t)p1.x * 128);
        float4 u0 = __ldg(r0 + c);
        float4 u1 = __ldg(r0 + c + 8);
        float4 v0 = __ldg(r1 + c);
        float4 v1 = __ldg(r1 + c + 8);
        float w0 = __int_as_float(p0.y);
        float w1 = __int_as_float(p1.y);
        a0.x += w0 * u0.x; a0.y += w0 * u0.y; a0.z += w0 * u0.z; a0.w += w0 * u0.w;
        a1.x += w0 * u1.x; a1.y += w0 * u1.y; a1.z += w0 * u1.z; a1.w += w0 * u1.w;
        a0.x += w1 * v0.x; a0.y += w1 * v0.y; a0.z += w1 * v0.z; a0.w += w1 * v0.w;
        a1.x += w1 * v1.x; a1.y += w1 * v1.y; a1.z += w1 * v1.z; a1.w += w1 * v1.w;
    }
    if (i < end) {
        int2 p0 = __ldg(csr + i);
        const float4* r0 = (const float4*)(C + (size_t)p0.x * 128);
        float4 u0 = __ldg(r0 + c);
        float4 u1 = __ldg(r0 + c + 8);
        float w0 = __int_as_float(p0.y);
        a0.x += w0 * u0.x; a0.y += w0 * u0.y; a0.z += w0 * u0.z; a0.w += w0 * u0.w;
        a1.x += w0 * u1.x; a1.y += w0 * u1.y; a1.z += w0 * u1.z; a1.w += w0 * u1.w;
    }
    const float4* rp = (const float4*)(C + (size_t)node * 128) + 16;
    float4 rv0 = __ldg(rp + c);
    float4 rv1 = __ldg(rp + c + 8);
    a0.x += rv0.x; a0.y += rv0.y; a0.z += rv0.z; a0.w += rv0.w;
    a1.x += rv1.x; a1.y += rv1.y; a1.z += rv1.z; a1.w += rv1.w;
    if (do_relu) {
        a0.x = fmaxf(a0.x, 0.f); a0.y = fmaxf(a0.y, 0.f);
        a0.z = fmaxf(a0.z, 0.f); a0.w = fmaxf(a0.w, 0.f);
        a1.x = fmaxf(a1.x, 0.f); a1.y = fmaxf(a1.y, 0.f);
        a1.z = fmaxf(a1.z, 0.f); a1.w = fmaxf(a1.w, 0.f);
    }
    if (out32) {
        float4* op = (float4*)(out32 + (size_t)node * 64);
        op[c] = a0;
        op[c + 8] = a1;
    }
    if (split) {
        __half* sp = split + (size_t)node * 128;
        int f0 = 4 * c, f1 = 32 + 4 * c;
        __half hx, hy, hz, hw;
        hx = __float2half_rn(a0.x); hy = __float2half_rn(a0.y);
        hz = __float2half_rn(a0.z); hw = __float2half_rn(a0.w);
        *(__half2*)(sp + f0) = __halves2half2(hx, hy);
        *(__half2*)(sp + f0 + 2) = __halves2half2(hz, hw);
        *(__half2*)(sp + 64 + f0) = __halves2half2(
            __float2half_rn(a0.x - __half2float(hx)), __float2half_rn(a0.y - __half2float(hy)));
        *(__half2*)(sp + 64 + f0 + 2) = __halves2half2(
            __float2half_rn(a0.z - __half2float(hz)), __float2half_rn(a0.w - __half2float(hw)));
        hx = __float2half_rn(a1.x); hy = __float2half_rn(a1.y);
        hz = __float2half_rn(a1.z); hw = __float2half_rn(a1.w);
        *(__half2*)(sp + f1) = __halves2half2(hx, hy);
        *(__half2*)(sp + f1 + 2) = __halves2half2(hz, hw);
        *(__half2*)(sp + 64 + f1) = __halves2half2(
            __float2half_rn(a1.x - __half2float(hx)), __float2half_rn(a1.y - __half2float(hy)));
        *(__half2*)(sp + 64 + f1 + 2) = __halves2half2(
            __float2half_rn(a1.z - __half2float(hz)), __float2half_rn(a1.w - __half2float(hw)));
    }
}

// ---------------------------------------------------------------------------
// Decoder: pred[e] = relu(u[s]+v[d]) . dec_W2 + dec_b2 ; duplicated.
// uv: [N x 256] fp16, u = cols [0,128), v = cols [128,256). 16 thr/edge.
// ---------------------------------------------------------------------------
__global__ void decode_edges_h(const int* __restrict__ src, const int* __restrict__ dst,
                               const __half* __restrict__ uv,
                               const float* __restrict__ W2, const float* __restrict__ b2,
                               float* __restrict__ pred, int OBS) {
    int gt = blockIdx.x * blockDim.x + threadIdx.x;
    int e = gt >> 4;
    int c = gt & 15;
    if (e >= OBS) return;
    int s = src[e];
    int d = dst[e];
    uint4 ub = __ldg((const uint4*)(uv + (size_t)s * 256) + c);
    uint4 vb = __ldg((const uint4*)(uv + (size_t)d * 256 + 128) + c);
    float4 w0 = __ldg((const float4*)W2 + 2 * c);
    float4 w1 = __ldg((const float4*)W2 + 2 * c + 1);

    float2 fu0 = __half22float2(*(const half2*)&ub.x);
    float2 fu1 = __half22float2(*(const half2*)&ub.y);
    float2 fu2 = __half22float2(*(const half2*)&ub.z);
    float2 fu3 = __half22float2(*(const half2*)&ub.w);
    float2 fv0 = __half22float2(*(const half2*)&vb.x);
    float2 fv1 = __half22float2(*(const half2*)&vb.y);
    float2 fv2 = __half22float2(*(const half2*)&vb.z);
    float2 fv3 = __half22float2(*(const half2*)&vb.w);

    float acc = fmaxf(fu0.x + fv0.x, 0.f) * w0.x + fmaxf(fu0.y + fv0.y, 0.f) * w0.y
              + fmaxf(fu1.x + fv1.x, 0.f) * w0.z + fmaxf(fu1.y + fv1.y, 0.f) * w0.w
              + fmaxf(fu2.x + fv2.x, 0.f) * w1.x + fmaxf(fu2.y + fv2.y, 0.f) * w1.y
              + fmaxf(fu3.x + fv3.x, 0.f) * w1.z + fmaxf(fu3.y + fv3.y, 0.f) * w1.w;
#pragma unroll
    for (int o = 8; o > 0; o >>= 1) acc += __shfl_xor_sync(0xFFFFFFFFu, acc, o);
    if (c == 0) {
        float p = acc + __ldg(b2);
        pred[e] = p;
        pred[e + OBS] = p;
    }
}

// ---------------------------------------------------------------------------
// Launch
// ---------------------------------------------------------------------------
extern "C" void kernel_launch(void* const* d_in, const int* in_sizes, int n_in,
                              void* d_out, int out_size) {
    const float* x       = (const float*)d_in[0];
    const int*   ei      = (const int*)d_in[1];
    const float* ew      = (const float*)d_in[2];
    const float* W1_rel  = (const float*)d_in[4];
    const float* b1      = (const float*)d_in[5];
    const float* W1_root = (const float*)d_in[6];
    const float* W2_rel  = (const float*)d_in[7];
    const float* b2      = (const float*)d_in[8];
    const float* W2_root = (const float*)d_in[9];
    const float* W3_rel  = (const float*)d_in[10];
    const float* b3      = (const float*)d_in[11];
    const float* W3_root = (const float*)d_in[12];
    const float* dW1     = (const float*)d_in[13];
    const float* db1     = (const float*)d_in[14];
    const float* dW2     = (const float*)d_in[15];
    const float* db2     = (const float*)d_in[16];

    int N   = in_sizes[0] / 2;
    int E   = in_sizes[2];
    int OBS = E / 2;

    const int* src = ei;
    const int* dst = ei + E;

    float* out = (float*)d_out;
    float* z   = out + 2 * (size_t)OBS;

    float *agg1, *C, *bias2, *bias3, *biasd;
    __half *h1s, *h2s, *zs, *uv, *ws2, *ws3, *wsd;
    int *cnt, *roff, *cursor;
    int2* csr;
    cudaGetSymbolAddress((void**)&agg1,   g_agg1);
    cudaGetSymbolAddress((void**)&h1s,    g_h1s);
    cudaGetSymbolAddress((void**)&C,      g_C);
    cudaGetSymbolAddress((void**)&h2s,    g_h2s);
    cudaGetSymbolAddress((void**)&zs,     g_zs);
    cudaGetSymbolAddress((void**)&uv,     g_uv);
    cudaGetSymbolAddress((void**)&ws2,    g_ws2);
    cudaGetSymbolAddress((void**)&ws3,    g_ws3);
    cudaGetSymbolAddress((void**)&wsd,    g_wsd);
    cudaGetSymbolAddress((void**)&bias2,  g_bias2);
    cudaGetSymbolAddress((void**)&bias3,  g_bias3);
    cudaGetSymbolAddress((void**)&biasd,  g_biasd);
    cudaGetSymbolAddress((void**)&cnt,    g_cnt);
    cudaGetSymbolAddress((void**)&roff,   g_roff);
    cudaGetSymbolAddress((void**)&cursor, g_cursor);
    cudaGetSymbolAddress((void**)&csr,    g_csr);

    const int TB = 256;
    int eb = (E + TB - 1) / TB;
    int mblocks = (N + 63) / 64;

    // ---- weight/bias prep (tiny) ----
    prep_split<<<(128 * 128 + TB - 1) / TB, TB>>>(W2_rel, W2_root, ws2, 128, 128, 64, 64);
    prep_split<<<(64 * 128 + TB - 1) / TB, TB>>>(W3_rel, W3_root, ws3, 64, 128, 64, 64);
    prep_split<<<(64 * 256 + TB - 1) / TB, TB>>>(dW1, dW1 + 64 * 128, wsd, 64, 256, 128, 128);
    prep_bias<<<1, 128>>>(b2, bias2, 64, 64, 128);
    prep_bias<<<1, 128>>>(b3, bias3, 64, 64, 128);
    prep_bias<<<1, 256>>>(db1, biasd, 0, 128, 256);

    // ---- Build dst-sorted CSR ----
    cudaMemsetAsync(cnt, 0, (size_t)N * sizeof(int));
    hist_kernel<<<eb, TB>>>(dst, cnt, E);
    scan_counts<<<1, 1024>>>(cnt, roff, cursor, N);
    fill_kernel<<<eb, TB>>>(src, dst, ew, cursor, csr, E);

    // ---- Layer 1 ----
    gather_l1<<<(N * 4 + TB - 1) / TB, TB>>>(csr, roff, x, agg1, N);
    layer1_kernel<<<(N * 64 + TB - 1) / TB, TB>>>(x, agg1, W1_rel, W1_root, b1, h1s, N);

    // ---- Layer 2: tensor gemm (128->[y64|r64]) + fused gather ----
    {
        dim3 grid(mblocks, 2);
        gemm_wmma<128, 128, float><<<grid, 128>>>(h1s, ws2, bias2, C, N);
    }
    gather64<<<(N + 31) / 32, TB>>>(csr, roff, C, nullptr, h2s, N, 1);

    // ---- Layer 3 ----
    {
        dim3 grid(mblocks, 2);
        gemm_wmma<64, 128, float><<<grid, 128>>>(h2s, ws3, bias3, C, N);
    }
    gather64<<<(N + 31) / 32, TB>>>(csr, roff, C, z, zs, N, 0);

    // ---- Decoder ----
    {
        dim3 grid(mblocks, 4);
        gemm_wmma<64, 256, __half><<<grid, 128>>>(zs, wsd, biasd, uv, N);
    }
    decode_edges_h<<<((size_t)OBS * 16 + TB - 1) / TB, TB>>>(src, dst, uv, dW2, db2, out, OBS);
}

// round 4
// speedup vs baseline: 1.3502x; 1.3502x over previous
#include <cuda_runtime.h>
#include <cuda_fp16.h>
#include <mma.h>
#include <cstddef>

using namespace nvcuda;

// ---------------------------------------------------------------------------
// Static scratch
// ---------------------------------------------------------------------------
#define NMAX 50000
#define CAP  192

__device__ __half g_h1s[(size_t)NMAX * 256];   // layer1 out, split fp16 [hi128|lo128]
__device__ float  g_C[(size_t)NMAX * 128];     // gemm out [y64|r64] fp32
__device__ __half g_h2s[(size_t)NMAX * 128];   // h2 split [hi64|lo64]
__device__ __half g_zs[(size_t)NMAX * 128];    // z split  [hi64|lo64]
__device__ __half g_uv[(size_t)NMAX * 256];    // decoder [u128|v128] fp16

// split weights + biases
__device__ __half g_ws2[256 * 128];
__device__ __half g_ws3[128 * 128];
__device__ __half g_wsd[128 * 256];
__device__ float  g_bias2[128];
__device__ float  g_bias3[128];
__device__ float  g_biasd[256];

// bucketed CSR
__device__ int  g_cursor[NMAX];
__device__ int2 g_csr[(size_t)NMAX * CAP];

// ---------------------------------------------------------------------------
// Single prep kernel: all weight splits + all biases
// ---------------------------------------------------------------------------
__global__ void prep_all(const float* __restrict__ W2_rel, const float* __restrict__ W2_root,
                         const float* __restrict__ W3_rel, const float* __restrict__ W3_root,
                         const float* __restrict__ dW1,
                         const float* __restrict__ b2, const float* __restrict__ b3,
                         const float* __restrict__ db1,
                         __half* __restrict__ ws2, __half* __restrict__ ws3,
                         __half* __restrict__ wsd,
                         float* __restrict__ bias2, float* __restrict__ bias3,
                         float* __restrict__ biasd) {
    int i = blockIdx.x * blockDim.x + threadIdx.x;
    // segment sizes
    const int A = 128 * 128;       // ws2 (K=128, OUT=128)
    const int B = 64 * 128;        // ws3 (K=64, OUT=128)
    const int Cc = 64 * 256;       // wsd (K=64, OUT=256)
    if (i < A) {
        int k = i >> 7, j = i & 127;
        float v = (j < 64) ? W2_rel[k * 64 + j] : W2_root[k * 64 + (j - 64)];
        __half hi = __float2half_rn(v);
        ws2[(size_t)k * 128 + j] = hi;
        ws2[(size_t)(128 + k) * 128 + j] = __float2half_rn(v - __half2float(hi));
        return;
    }
    i -= A;
    if (i < B) {
        int k = i >> 7, j = i & 127;
        float v = (j < 64) ? W3_rel[k * 64 + j] : W3_root[k * 64 + (j - 64)];
        __half hi = __float2half_rn(v);
        ws3[(size_t)k * 128 + j] = hi;
        ws3[(size_t)(64 + k) * 128 + j] = __float2half_rn(v - __half2float(hi));
        return;
    }
    i -= B;
    if (i < Cc) {
        int k = i >> 8, j = i & 255;
        float v = dW1[k * 128 + (j & 127) + ((j >> 7) ? 64 * 128 : 0)];
        __half hi = __float2half_rn(v);
        wsd[(size_t)k * 256 + j] = hi;
        wsd[(size_t)(64 + k) * 256 + j] = __float2half_rn(v - __half2float(hi));
        return;
    }
    i -= Cc;
    if (i < 128) { bias2[i] = (i >= 64) ? b2[i - 64] : 0.f; return; }
    i -= 128;
    if (i < 128) { bias3[i] = (i >= 64) ? b3[i - 64] : 0.f; return; }
    i -= 128;
    if (i < 256) { biasd[i] = (i < 128) ? db1[i] : 0.f; return; }
}

// ---------------------------------------------------------------------------
// Bucketed CSR fill: csr[d*CAP + slot] = (src, bits(ew)); cursor = per-dst count
// ---------------------------------------------------------------------------
__global__ void fill_kernel(const int* __restrict__ src, const int* __restrict__ dst,
                            const float* __restrict__ ew, int* __restrict__ cursor,
                            int2* __restrict__ csr, int E) {
    int e = blockIdx.x * blockDim.x + threadIdx.x;
    if (e >= E) return;
    int d = dst[e];
    int p = atomicAdd(&cursor[d], 1);
    if (p < CAP) csr[(size_t)d * CAP + p] = make_int2(src[e], __float_as_int(ew[e]));
}

// ---------------------------------------------------------------------------
// Fused layer-1: quad-gather agg (2 feats) + expand to split fp16 128 feats.
// 4 lanes/node; after quad reduce each lane writes 32 features.
// ---------------------------------------------------------------------------
__global__ void layer1_fused(const int2* __restrict__ csr, const int* __restrict__ cnt,
                             const float* __restrict__ x,
                             const float* __restrict__ W1_rel,
                             const float* __restrict__ W1_root,
                             const float* __restrict__ b1,
                             __half* __restrict__ h1s, int N) {
    int tid = blockIdx.x * blockDim.x + threadIdx.x;
    int n = tid >> 2;
    int l = tid & 3;
    if (n >= N) return;
    int deg = __ldg(cnt + n);
    const int2* bkt = csr + (size_t)n * CAP;
    float a0 = 0.f, a1 = 0.f;
    for (int i = l; i < deg; i += 4) {
        int2 p = __ldg(bkt + i);
        float w = __int_as_float(p.y);
        float2 xv = __ldg((const float2*)(x + 2 * (size_t)p.x));
        a0 += w * xv.x;
        a1 += w * xv.y;
    }
#pragma unroll
    for (int o = 1; o < 4; o <<= 1) {
        a0 += __shfl_xor_sync(0xFFFFFFFFu, a0, o);
        a1 += __shfl_xor_sync(0xFFFFFFFFu, a1, o);
    }
    float2 xv = __ldg((const float2*)(x + 2 * (size_t)n));
    __half* hp = h1s + (size_t)n * 256;
#pragma unroll 4
    for (int j = 0; j < 16; j++) {
        int f = l * 32 + 2 * j;
        float v0 = a0 * __ldg(W1_rel + f) + a1 * __ldg(W1_rel + 128 + f)
                 + xv.x * __ldg(W1_root + f) + xv.y * __ldg(W1_root + 128 + f) + __ldg(b1 + f);
        float v1 = a0 * __ldg(W1_rel + f + 1) + a1 * __ldg(W1_rel + 129 + f)
                 + xv.x * __ldg(W1_root + f + 1) + xv.y * __ldg(W1_root + 129 + f) + __ldg(b1 + f + 1);
        v0 = fmaxf(v0, 0.f);
        v1 = fmaxf(v1, 0.f);
        __half h0 = __float2half_rn(v0), h1 = __float2half_rn(v1);
        *(__half2*)(hp + f) = __halves2half2(h0, h1);
        *(__half2*)(hp + 128 + f) = __halves2half2(
            __float2half_rn(v0 - __half2float(h0)), __float2half_rn(v1 - __half2float(h1)));
    }
}

// ---------------------------------------------------------------------------
// Resident-smem split-fp16 wmma GEMM.
//   C[64 x 64-tile] = sum over 3 segments of Hs-slab @ Ws-slab + bias
// Hs: [N x 2K] fp16 (hi cols [0,K), lo cols [K,2K))
// Ws: [2K x OUT] fp16 (hi rows [0,K), lo rows [K,2K))
// Both operand slabs loaded to smem ONCE, then 3*K/16 mma steps, no reloads.
// ---------------------------------------------------------------------------
template <int K, int OUT, typename TOut>
__global__ void gemm_res(const __half* __restrict__ Hs,
                         const __half* __restrict__ Ws,
                         const float* __restrict__ bias,
                         TOut* __restrict__ C, int N) {
    constexpr int K2 = 2 * K;
    constexpr int LDH = K2 + 8;
    constexpr int LDW = 72;
    extern __shared__ char smem_raw[];
    __half* sh_h = (__half*)smem_raw;                       // 64 x LDH
    __half* sh_w = (__half*)(smem_raw + (size_t)64 * LDH * 2);  // K2 x LDW
    float*  sh_c = (float*)smem_raw;                        // epilogue reuse (16KB)

    int m0 = blockIdx.x * 64;
    int n0 = blockIdx.y * 64;
    int t = threadIdx.x;  // 128

    // Load H slab (64 rows x K2 halves), coalesced by row-contiguous uint4
    constexpr int RV = K2 / 8;  // uint4 per H row
    for (int i = t; i < 64 * RV; i += 128) {
        int row = i / RV, col = i - row * RV;
        int n = m0 + row;
        uint4 v = make_uint4(0, 0, 0, 0);
        if (n < N) v = *(const uint4*)(Hs + (size_t)n * K2 + col * 8);
        *(uint4*)(sh_h + row * LDH + col * 8) = v;
    }
    // Load W slab (K2 rows x 64 cols)
    for (int i = t; i < K2 * 8; i += 128) {
        int row = i >> 3, col = i & 7;
        *(uint4*)(sh_w + row * LDW + col * 8) =
            *(const uint4*)(Ws + (size_t)row * OUT + n0 + col * 8);
    }
    __syncthreads();

    int warp = t >> 5;
    int wm = (warp & 1) * 32, wn = (warp >> 1) * 32;

    wmma::fragment<wmma::accumulator, 16, 16, 16, float> acc[2][2];
#pragma unroll
    for (int i = 0; i < 2; i++)
#pragma unroll
        for (int j = 0; j < 2; j++) wmma::fill_fragment(acc[i][j], 0.f);

    constexpr int NKT = K / 16;
#pragma unroll
    for (int t3 = 0; t3 < 3 * NKT; t3++) {
        int seg = t3 / NKT, kt = t3 - seg * NKT;
        int hc = (seg == 1 ? K : 0) + kt * 16;  // H cols: hi,lo,hi
        int wr = (seg == 2 ? K : 0) + kt * 16;  // W rows: hi,hi,lo
        wmma::fragment<wmma::matrix_a, 16, 16, 16, __half, wmma::row_major> a0, a1;
        wmma::fragment<wmma::matrix_b, 16, 16, 16, __half, wmma::row_major> b0, b1;
        wmma::load_matrix_sync(a0, sh_h + (wm + 0) * LDH + hc, LDH);
        wmma::load_matrix_sync(a1, sh_h + (wm + 16) * LDH + hc, LDH);
        wmma::load_matrix_sync(b0, sh_w + wr * LDW + wn, LDW);
        wmma::load_matrix_sync(b1, sh_w + wr * LDW + wn + 16, LDW);
        wmma::mma_sync(acc[0][0], a0, b0, acc[0][0]);
        wmma::mma_sync(acc[0][1], a0, b1, acc[0][1]);
        wmma::mma_sync(acc[1][0], a1, b0, acc[1][0]);
        wmma::mma_sync(acc[1][1], a1, b1, acc[1][1]);
    }
    __syncthreads();  // done reading sh_h before reuse as sh_c
#pragma unroll
    for (int i = 0; i < 2; i++)
#pragma unroll
        for (int j = 0; j < 2; j++)
            wmma::store_matrix_sync(sh_c + (wm + i * 16) * 64 + wn + j * 16,
                                    acc[i][j], 64, wmma::mem_row_major);
    __syncthreads();

    for (int idx = t; idx < 64 * 64; idx += 128) {
        int row = idx >> 6, col = idx & 63;
        int n = m0 + row;
        if (n < N) C[(size_t)n * OUT + n0 + col] = (TOut)(sh_c[idx] + __ldg(bias + n0 + col));
    }
}

// ---------------------------------------------------------------------------
// Fused gather + residual + act. C holds [y64|r64] rows of 128 fp32.
// 8 lanes/node; writes fp32 out (optional) and/or split fp16 (optional).
// ---------------------------------------------------------------------------
__global__ void gather64(const int2* __restrict__ csr, const int* __restrict__ cnt,
                         const float* __restrict__ C, float* __restrict__ out32,
                         __half* __restrict__ split, int N, int do_relu) {
    int node = blockIdx.x * 32 + (threadIdx.x >> 3);
    int c = threadIdx.x & 7;
    if (node >= N) return;
    int deg = __ldg(cnt + node);
    const int2* bkt = csr + (size_t)node * CAP;
    float4 a0 = make_float4(0, 0, 0, 0);
    float4 a1 = make_float4(0, 0, 0, 0);
    int i = 0;
    for (; i + 2 <= deg; i += 2) {
        int2 p0 = __ldg(bkt + i);
        int2 p1 = __ldg(bkt + i + 1);
        const float4* r0 = (const float4*)(C + (size_t)p0.x * 128);
        const float4* r1 = (const float4*)(C + (size_t)p1.x * 128);
        float4 u0 = __ldg(r0 + c);
        float4 u1 = __ldg(r0 + c + 8);
        float4 v0 = __ldg(r1 + c);
        float4 v1 = __ldg(r1 + c + 8);
        float w0 = __int_as_float(p0.y);
        float w1 = __int_as_float(p1.y);
        a0.x += w0 * u0.x; a0.y += w0 * u0.y; a0.z += w0 * u0.z; a0.w += w0 * u0.w;
        a1.x += w0 * u1.x; a1.y += w0 * u1.y; a1.z += w0 * u1.z; a1.w += w0 * u1.w;
        a0.x += w1 * v0.x; a0.y += w1 * v0.y; a0.z += w1 * v0.z; a0.w += w1 * v0.w;
        a1.x += w1 * v1.x; a1.y += w1 * v1.y; a1.z += w1 * v1.z; a1.w += w1 * v1.w;
    }
    if (i < deg) {
        int2 p0 = __ldg(bkt + i);
        const float4* r0 = (const float4*)(C + (size_t)p0.x * 128);
        float4 u0 = __ldg(r0 + c);
        float4 u1 = __ldg(r0 + c + 8);
        float w0 = __int_as_float(p0.y);
        a0.x += w0 * u0.x; a0.y += w0 * u0.y; a0.z += w0 * u0.z; a0.w += w0 * u0.w;
        a1.x += w0 * u1.x; a1.y += w0 * u1.y; a1.z += w0 * u1.z; a1.w += w0 * u1.w;
    }
    const float4* rp = (const float4*)(C + (size_t)node * 128) + 16;
    float4 rv0 = __ldg(rp + c);
    float4 rv1 = __ldg(rp + c + 8);
    a0.x += rv0.x; a0.y += rv0.y; a0.z += rv0.z; a0.w += rv0.w;
    a1.x += rv1.x; a1.y += rv1.y; a1.z += rv1.z; a1.w += rv1.w;
    if (do_relu) {
        a0.x = fmaxf(a0.x, 0.f); a0.y = fmaxf(a0.y, 0.f);
        a0.z = fmaxf(a0.z, 0.f); a0.w = fmaxf(a0.w, 0.f);
        a1.x = fmaxf(a1.x, 0.f); a1.y = fmaxf(a1.y, 0.f);
        a1.z = fmaxf(a1.z, 0.f); a1.w = fmaxf(a1.w, 0.f);
    }
    if (out32) {
        float4* op = (float4*)(out32 + (size_t)node * 64);
        op[c] = a0;
        op[c + 8] = a1;
    }
    if (split) {
        __half* sp = split + (size_t)node * 128;
        int f0 = 4 * c, f1 = 32 + 4 * c;
        __half hx = __float2half_rn(a0.x), hy = __float2half_rn(a0.y);
        __half hz = __float2half_rn(a0.z), hw = __float2half_rn(a0.w);
        *(__half2*)(sp + f0) = __halves2half2(hx, hy);
        *(__half2*)(sp + f0 + 2) = __halves2half2(hz, hw);
        *(__half2*)(sp + 64 + f0) = __halves2half2(
            __float2half_rn(a0.x - __half2float(hx)), __float2half_rn(a0.y - __half2float(hy)));
        *(__half2*)(sp + 64 + f0 + 2) = __halves2half2(
            __float2half_rn(a0.z - __half2float(hz)), __float2half_rn(a0.w - __half2float(hw)));
        hx = __float2half_rn(a1.x); hy = __float2half_rn(a1.y);
        hz = __float2half_rn(a1.z); hw = __float2half_rn(a1.w);
        *(__half2*)(sp + f1) = __halves2half2(hx, hy);
        *(__half2*)(sp + f1 + 2) = __halves2half2(hz, hw);
        *(__half2*)(sp + 64 + f1) = __halves2half2(
            __float2half_rn(a1.x - __half2float(hx)), __float2half_rn(a1.y - __half2float(hy)));
        *(__half2*)(sp + 64 + f1 + 2) = __halves2half2(
            __float2half_rn(a1.z - __half2float(hz)), __float2half_rn(a1.w - __half2float(hw)));
    }
}

// ---------------------------------------------------------------------------
// Decoder: pred[e] = relu(u[s]+v[d]) . dec_W2 + dec_b2 ; duplicated.
// ---------------------------------------------------------------------------
__global__ void decode_edges_h(const int* __restrict__ src, const int* __restrict__ dst,
                               const __half* __restrict__ uv,
                               const float* __restrict__ W2, const float* __restrict__ b2,
                               float* __restrict__ pred, int OBS) {
    int gt = blockIdx.x * blockDim.x + threadIdx.x;
    int e = gt >> 4;
    int c = gt & 15;
    if (e >= OBS) return;
    int s = src[e];
    int d = dst[e];
    uint4 ub = __ldg((const uint4*)(uv + (size_t)s * 256) + c);
    uint4 vb = __ldg((const uint4*)(uv + (size_t)d * 256 + 128) + c);
    float4 w0 = __ldg((const float4*)W2 + 2 * c);
    float4 w1 = __ldg((const float4*)W2 + 2 * c + 1);

    float2 fu0 = __half22float2(*(const half2*)&ub.x);
    float2 fu1 = __half22float2(*(const half2*)&ub.y);
    float2 fu2 = __half22float2(*(const half2*)&ub.z);
    float2 fu3 = __half22float2(*(const half2*)&ub.w);
    float2 fv0 = __half22float2(*(const half2*)&vb.x);
    float2 fv1 = __half22float2(*(const half2*)&vb.y);
    float2 fv2 = __half22float2(*(const half2*)&vb.z);
    float2 fv3 = __half22float2(*(const half2*)&vb.w);

    float acc = fmaxf(fu0.x + fv0.x, 0.f) * w0.x + fmaxf(fu0.y + fv0.y, 0.f) * w0.y
              + fmaxf(fu1.x + fv1.x, 0.f) * w0.z + fmaxf(fu1.y + fv1.y, 0.f) * w0.w
              + fmaxf(fu2.x + fv2.x, 0.f) * w1.x + fmaxf(fu2.y + fv2.y, 0.f) * w1.y
              + fmaxf(fu3.x + fv3.x, 0.f) * w1.z + fmaxf(fu3.y + fv3.y, 0.f) * w1.w;
#pragma unroll
    for (int o = 8; o > 0; o >>= 1) acc += __shfl_xor_sync(0xFFFFFFFFu, acc, o);
    if (c == 0) {
        float p = acc + __ldg(b2);
        pred[e] = p;
        pred[e + OBS] = p;
    }
}

// ---------------------------------------------------------------------------
// Launch
// ---------------------------------------------------------------------------
extern "C" void kernel_launch(void* const* d_in, const int* in_sizes, int n_in,
                              void* d_out, int out_size) {
    const float* x       = (const float*)d_in[0];
    const int*   ei      = (const int*)d_in[1];
    const float* ew      = (const float*)d_in[2];
    const float* W1_rel  = (const float*)d_in[4];
    const float* b1      = (const float*)d_in[5];
    const float* W1_root = (const float*)d_in[6];
    const float* W2_rel  = (const float*)d_in[7];
    const float* b2      = (const float*)d_in[8];
    const float* W2_root = (const float*)d_in[9];
    const float* W3_rel  = (const float*)d_in[10];
    const float* b3      = (const float*)d_in[11];
    const float* W3_root = (const float*)d_in[12];
    const float* dW1     = (const float*)d_in[13];
    const float* db1     = (const float*)d_in[14];
    const float* dW2     = (const float*)d_in[15];
    const float* db2     = (const float*)d_in[16];

    int N   = in_sizes[0] / 2;
    int E   = in_sizes[2];
    int OBS = E / 2;

    const int* src = ei;
    const int* dst = ei + E;

    float* out = (float*)d_out;
    float* z   = out + 2 * (size_t)OBS;

    float *C, *bias2, *bias3, *biasd;
    __half *h1s, *h2s, *zs, *uv, *ws2, *ws3, *wsd;
    int *cursor;
    int2* csr;
    cudaGetSymbolAddress((void**)&h1s,    g_h1s);
    cudaGetSymbolAddress((void**)&C,      g_C);
    cudaGetSymbolAddress((void**)&h2s,    g_h2s);
    cudaGetSymbolAddress((void**)&zs,     g_zs);
    cudaGetSymbolAddress((void**)&uv,     g_uv);
    cudaGetSymbolAddress((void**)&ws2,    g_ws2);
    cudaGetSymbolAddress((void**)&ws3,    g_ws3);
    cudaGetSymbolAddress((void**)&wsd,    g_wsd);
    cudaGetSymbolAddress((void**)&bias2,  g_bias2);
    cudaGetSymbolAddress((void**)&bias3,  g_bias3);
    cudaGetSymbolAddress((void**)&biasd,  g_biasd);
    cudaGetSymbolAddress((void**)&cursor, g_cursor);
    cudaGetSymbolAddress((void**)&csr,    g_csr);

    // dynamic smem sizes
    const int SM128 = 64 * (2 * 128 + 8) * 2 + (2 * 128) * 72 * 2;  // 70656
    const int SM64  = 64 * (2 * 64 + 8) * 2 + (2 * 64) * 72 * 2;    // 35840
    static bool attr_done = false;
    if (!attr_done) {
        cudaFuncSetAttribute(gemm_res<128, 128, float>,
                             cudaFuncAttributeMaxDynamicSharedMemorySize, SM128);
        cudaFuncSetAttribute(gemm_res<64, 128, float>,
                             cudaFuncAttributeMaxDynamicSharedMemorySize, SM64);
        cudaFuncSetAttribute(gemm_res<64, 256, __half>,
                             cudaFuncAttributeMaxDynamicSharedMemorySize, SM64);
        attr_done = true;
    }

    const int TB = 256;
    int eb = (E + TB - 1) / TB;
    int mblocks = (N + 63) / 64;

    // ---- prep (1 launch) ----
    {
        int total = 128 * 128 + 64 * 128 + 64 * 256 + 128 + 128 + 256;
        prep_all<<<(total + TB - 1) / TB, TB>>>(W2_rel, W2_root, W3_rel, W3_root, dW1,
                                                b2, b3, db1, ws2, ws3, wsd,
                                                bias2, bias3, biasd);
    }

    // ---- Bucketed CSR ----
    cudaMemsetAsync(cursor, 0, (size_t)N * sizeof(int));
    fill_kernel<<<eb, TB>>>(src, dst, ew, cursor, csr, E);

    // ---- Layer 1 fused ----
    layer1_fused<<<(N * 4 + TB - 1) / TB, TB>>>(csr, cursor, x, W1_rel, W1_root, b1, h1s, N);

    // ---- Layer 2 ----
    {
        dim3 grid(mblocks, 2);
        gemm_res<128, 128, float><<<grid, 128, SM128>>>(h1s, ws2, bias2, C, N);
    }
    gather64<<<(N + 31) / 32, TB>>>(csr, cursor, C, nullptr, h2s, N, 1);

    // ---- Layer 3 ----
    {
        dim3 grid(mblocks, 2);
        gemm_res<64, 128, float><<<grid, 128, SM64>>>(h2s, ws3, bias3, C, N);
    }
    gather64<<<(N + 31) / 32, TB>>>(csr, cursor, C, z, zs, N, 0);

    // ---- Decoder ----
    {
        dim3 grid(mblocks, 4);
        gemm_res<64, 256, __half><<<grid, 128, SM64>>>(zs, wsd, biasd, uv, N);
    }
    decode_edges_h<<<((size_t)OBS * 16 + TB - 1) / TB, TB>>>(src, dst, uv, dW2, db2, out, OBS);
}

// round 6
// speedup vs baseline: 1.5177x; 1.1241x over previous
#include <cuda_runtime.h>
#include <cuda_fp16.h>
#include <mma.h>
#include <cstddef>
#include <cstdint>

using namespace nvcuda;

// ---------------------------------------------------------------------------
// Static scratch (padded to NPAD rows so gemm loads/stores are branch-free)
// ---------------------------------------------------------------------------
#define NMAX 50000
#define NPAD 50176
#define CAP  192

__device__ __half g_h1s[(size_t)NPAD * 256];   // layer1 out, split fp16 [hi128|lo128]
__device__ float  g_C[(size_t)NPAD * 128];     // gemm out [y64|r64] fp32
__device__ __half g_h2s[(size_t)NPAD * 128];   // h2 split [hi64|lo64]
__device__ __half g_zs[(size_t)NPAD * 128];    // z split  [hi64|lo64]
__device__ __half g_uv[(size_t)NPAD * 256];    // decoder [u128|v128] fp16

// split weights + biases
__device__ __half g_ws2[256 * 128];
__device__ __half g_ws3[128 * 128];
__device__ __half g_wsd[128 * 256];
__device__ float  g_bias2[128];
__device__ float  g_bias3[128];
__device__ float  g_biasd[256];

// bucketed CSR
__device__ int  g_cursor[NMAX];
__device__ int2 g_csr[(size_t)NMAX * CAP];

// ---------------------------------------------------------------------------
// cp.async helpers
// ---------------------------------------------------------------------------
__device__ __forceinline__ void cp16(void* smem, const void* gptr) {
    unsigned int s = (unsigned int)__cvta_generic_to_shared(smem);
    asm volatile("cp.async.ca.shared.global [%0], [%1], 16;\n" :: "r"(s), "l"(gptr));
}
__device__ __forceinline__ void cp_commit() {
    asm volatile("cp.async.commit_group;\n");
}
template <int n>
__device__ __forceinline__ void cp_wait() {
    asm volatile("cp.async.wait_group %0;\n" :: "n"(n));
}

// ---------------------------------------------------------------------------
// Single prep kernel: all weight splits + all biases
// ---------------------------------------------------------------------------
__global__ void prep_all(const float* __restrict__ W2_rel, const float* __restrict__ W2_root,
                         const float* __restrict__ W3_rel, const float* __restrict__ W3_root,
                         const float* __restrict__ dW1,
                         const float* __restrict__ b2, const float* __restrict__ b3,
                         const float* __restrict__ db1,
                         __half* __restrict__ ws2, __half* __restrict__ ws3,
                         __half* __restrict__ wsd,
                         float* __restrict__ bias2, float* __restrict__ bias3,
                         float* __restrict__ biasd) {
    int i = blockIdx.x * blockDim.x + threadIdx.x;
    const int A = 128 * 128;
    const int B = 64 * 128;
    const int Cc = 64 * 256;
    if (i < A) {
        int k = i >> 7, j = i & 127;
        float v = (j < 64) ? W2_rel[k * 64 + j] : W2_root[k * 64 + (j - 64)];
        __half hi = __float2half_rn(v);
        ws2[(size_t)k * 128 + j] = hi;
        ws2[(size_t)(128 + k) * 128 + j] = __float2half_rn(v - __half2float(hi));
        return;
    }
    i -= A;
    if (i < B) {
        int k = i >> 7, j = i & 127;
        float v = (j < 64) ? W3_rel[k * 64 + j] : W3_root[k * 64 + (j - 64)];
        __half hi = __float2half_rn(v);
        ws3[(size_t)k * 128 + j] = hi;
        ws3[(size_t)(64 + k) * 128 + j] = __float2half_rn(v - __half2float(hi));
        return;
    }
    i -= B;
    if (i < Cc) {
        int k = i >> 8, j = i & 255;
        float v = dW1[k * 128 + (j & 127) + ((j >> 7) ? 64 * 128 : 0)];
        __half hi = __float2half_rn(v);
        wsd[(size_t)k * 256 + j] = hi;
        wsd[(size_t)(64 + k) * 256 + j] = __float2half_rn(v - __half2float(hi));
        return;
    }
    i -= Cc;
    if (i < 128) { bias2[i] = (i >= 64) ? b2[i - 64] : 0.f; return; }
    i -= 128;
    if (i < 128) { bias3[i] = (i >= 64) ? b3[i - 64] : 0.f; return; }
    i -= 128;
    if (i < 256) { biasd[i] = (i < 128) ? db1[i] : 0.f; return; }
}

// ---------------------------------------------------------------------------
// Bucketed CSR fill
// ---------------------------------------------------------------------------
__global__ void fill_kernel(const int* __restrict__ src, const int* __restrict__ dst,
                            const float* __restrict__ ew, int* __restrict__ cursor,
                            int2* __restrict__ csr, int E) {
    int e = blockIdx.x * blockDim.x + threadIdx.x;
    if (e >= E) return;
    int d = dst[e];
    int p = atomicAdd(&cursor[d], 1);
    if (p < CAP) csr[(size_t)d * CAP + p] = make_int2(src[e], __float_as_int(ew[e]));
}

// ---------------------------------------------------------------------------
// Fused layer-1: quad-gather + expand to split fp16 (2 -> 128)
// ---------------------------------------------------------------------------
__global__ void layer1_fused(const int2* __restrict__ csr, const int* __restrict__ cnt,
                             const float* __restrict__ x,
                             const float* __restrict__ W1_rel,
                             const float* __restrict__ W1_root,
                             const float* __restrict__ b1,
                             __half* __restrict__ h1s, int N) {
    int tid = blockIdx.x * blockDim.x + threadIdx.x;
    int n = tid >> 2;
    int l = tid & 3;
    if (n >= N) return;
    int deg = __ldg(cnt + n);
    const int2* bkt = csr + (size_t)n * CAP;
    float a0 = 0.f, a1 = 0.f;
    for (int i = l; i < deg; i += 4) {
        int2 p = __ldg(bkt + i);
        float w = __int_as_float(p.y);
        float2 xv = __ldg((const float2*)(x + 2 * (size_t)p.x));
        a0 += w * xv.x;
        a1 += w * xv.y;
    }
#pragma unroll
    for (int o = 1; o < 4; o <<= 1) {
        a0 += __shfl_xor_sync(0xFFFFFFFFu, a0, o);
        a1 += __shfl_xor_sync(0xFFFFFFFFu, a1, o);
    }
    float2 xv = __ldg((const float2*)(x + 2 * (size_t)n));
    __half* hp = h1s + (size_t)n * 256;
#pragma unroll 4
    for (int j = 0; j < 16; j++) {
        int f = l * 32 + 2 * j;
        float v0 = a0 * __ldg(W1_rel + f) + a1 * __ldg(W1_rel + 128 + f)
                 + xv.x * __ldg(W1_root + f) + xv.y * __ldg(W1_root + 128 + f) + __ldg(b1 + f);
        float v1 = a0 * __ldg(W1_rel + f + 1) + a1 * __ldg(W1_rel + 129 + f)
                 + xv.x * __ldg(W1_root + f + 1) + xv.y * __ldg(W1_root + 129 + f) + __ldg(b1 + f + 1);
        v0 = fmaxf(v0, 0.f);
        v1 = fmaxf(v1, 0.f);
        __half h0 = __float2half_rn(v0), h1 = __float2half_rn(v1);
        *(__half2*)(hp + f) = __halves2half2(h0, h1);
        *(__half2*)(hp + 128 + f) = __halves2half2(
            __float2half_rn(v0 - __half2float(h0)), __float2half_rn(v1 - __half2float(h1)));
    }
}

// ---------------------------------------------------------------------------
// Pipelined split-fp16 wmma GEMM (cp.async double buffer).
//   M-tile 128, N-tile 64, K-tile 32, 8 warps @ 32x32.
// Hs: [NPAD x 2K] fp16 (hi cols [0,K), lo [K,2K)); Ws: [2K x OUT].
// 3 segments: (Hhi,Whi), (Hlo,Whi), (Hhi,Wlo). Bias preloaded into acc.
// fp32 out: direct fragment->global store. fp16 out: smem convert epilogue.
// ---------------------------------------------------------------------------
template <int K, int OUT, typename TOut>
__global__ __launch_bounds__(256) void gemm_pipe(const __half* __restrict__ Hs,
                                                 const __half* __restrict__ Ws,
                                                 const float* __restrict__ bias,
                                                 TOut* __restrict__ C) {
    constexpr int K2 = 2 * K;
    constexpr int NKT = K / 32;        // k-tiles per segment
    constexpr int TOT = 3 * NKT;
    constexpr int LDH = 40;            // 32 + 8 pad (halves)
    constexpr int LDW = 72;            // 64 + 8 pad
    constexpr size_t HB = 128 * LDH;   // halves per H buffer
    constexpr size_t WB = 32 * LDW;

    extern __shared__ char smem_raw[];
    __half* sh_h = (__half*)smem_raw;                     // [2][HB]
    __half* sh_w = (__half*)(smem_raw + 2 * HB * 2);      // [2][WB]
    float*  sh_b = (float*)(smem_raw + 2 * HB * 2 + 2 * WB * 2);  // [16*64]
    float*  sh_c = (float*)smem_raw;                      // epilogue reuse

    int m0 = blockIdx.x * 128;
    int n0 = blockIdx.y * 64;
    int t = threadIdx.x;      // 256
    int warp = t >> 5;
    int wm = (warp & 3) * 32, wn = (warp >> 2) * 32;

    // bias tile: 16 rows x 64 cols, all rows identical
    {
        int r = t >> 4, c4 = (t & 15) * 4;
        float4 bv = *(const float4*)(bias + n0 + c4);
        *(float4*)(sh_b + r * 64 + c4) = bv;
    }

    // async load of a k-step into buffer `buf`
    auto load_step = [&](int step, int buf) {
        int seg = step / NKT, kt = step - seg * NKT;
        int hc = (seg == 1 ? K : 0) + kt * 32;
        int wr = (seg == 2 ? K : 0) + kt * 32;
        __half* hb = sh_h + buf * HB;
        __half* wb = sh_w + buf * WB;
        // H tile: 128 rows x 32 halves = 512 x 16B chunks, 2 per thread
#pragma unroll
        for (int i = 0; i < 2; i++) {
            int idx = t + i * 256;
            int row = idx >> 2, ch = idx & 3;
            cp16(hb + row * LDH + ch * 8, Hs + (size_t)(m0 + row) * K2 + hc + ch * 8);
        }
        // W tile: 32 rows x 64 halves = 256 x 16B chunks, 1 per thread
        {
            int row = t >> 3, ch = t & 7;
            cp16(wb + row * LDW + ch * 8, Ws + (size_t)(wr + row) * OUT + n0 + ch * 8);
        }
    };

    load_step(0, 0);
    cp_commit();

    __syncthreads();  // bias tile visible
    wmma::fragment<wmma::accumulator, 16, 16, 16, float> acc[2][2];
#pragma unroll
    for (int i = 0; i < 2; i++)
#pragma unroll
        for (int j = 0; j < 2; j++)
            wmma::load_matrix_sync(acc[i][j], sh_b + wn + j * 16, 64, wmma::mem_row_major);

    for (int step = 0; step < TOT; step++) {
        int cur = step & 1;
        if (step + 1 < TOT) load_step(step + 1, cur ^ 1);
        cp_commit();
        cp_wait<1>();
        __syncthreads();
        const __half* hb = sh_h + cur * HB;
        const __half* wb = sh_w + cur * WB;
#pragma unroll
        for (int kk = 0; kk < 32; kk += 16) {
            wmma::fragment<wmma::matrix_a, 16, 16, 16, __half, wmma::row_major> a0, a1;
            wmma::fragment<wmma::matrix_b, 16, 16, 16, __half, wmma::row_major> b0, b1;
            wmma::load_matrix_sync(a0, hb + (wm + 0) * LDH + kk, LDH);
            wmma::load_matrix_sync(a1, hb + (wm + 16) * LDH + kk, LDH);
            wmma::load_matrix_sync(b0, wb + kk * LDW + wn, LDW);
            wmma::load_matrix_sync(b1, wb + kk * LDW + wn + 16, LDW);
            wmma::mma_sync(acc[0][0], a0, b0, acc[0][0]);
            wmma::mma_sync(acc[0][1], a0, b1, acc[0][1]);
            wmma::mma_sync(acc[1][0], a1, b0, acc[1][0]);
            wmma::mma_sync(acc[1][1], a1, b1, acc[1][1]);
        }
        __syncthreads();
    }

    if constexpr (sizeof(TOut) == 4) {
        // fp32: store fragments straight to global (rows padded to NPAD)
#pragma unroll
        for (int i = 0; i < 2; i++)
#pragma unroll
            for (int j = 0; j < 2; j++)
                wmma::store_matrix_sync((float*)C + (size_t)(m0 + wm + i * 16) * OUT + n0 + wn + j * 16,
                                        acc[i][j], OUT, wmma::mem_row_major);
    } else {
        // fp16: smem round-trip + convert
#pragma unroll
        for (int i = 0; i < 2; i++)
#pragma unroll
            for (int j = 0; j < 2; j++)
                wmma::store_matrix_sync(sh_c + (size_t)(wm + i * 16) * 64 + wn + j * 16,
                                        acc[i][j], 64, wmma::mem_row_major);
        __syncthreads();
        for (int idx = t; idx < 128 * 64; idx += 256) {
            int row = idx >> 6, col = idx & 63;
            ((__half*)C)[(size_t)(m0 + row) * OUT + n0 + col] = __float2half_rn(sh_c[idx]);
        }
    }
}

// ---------------------------------------------------------------------------
// Fused gather + residual + act. C holds [y64|r64] rows of 128 fp32.
// ---------------------------------------------------------------------------
__global__ void gather64(const int2* __restrict__ csr, const int* __restrict__ cnt,
                         const float* __restrict__ C, float* __restrict__ out32,
                         __half* __restrict__ split, int N, int do_relu) {
    int node = blockIdx.x * 32 + (threadIdx.x >> 3);
    int c = threadIdx.x & 7;
    if (node >= N) return;
    int deg = __ldg(cnt + node);
    const int2* bkt = csr + (size_t)node * CAP;
    float4 a0 = make_float4(0, 0, 0, 0);
    float4 a1 = make_float4(0, 0, 0, 0);
    int i = 0;
    for (; i + 2 <= deg; i += 2) {
        int2 p0 = __ldg(bkt + i);
        int2 p1 = __ldg(bkt + i + 1);
        const float4* r0 = (const float4*)(C + (size_t)p0.x * 128);
        const float4* r1 = (const float4*)(C + (size_t)p1.x * 128);
        float4 u0 = __ldg(r0 + c);
        float4 u1 = __ldg(r0 + c + 8);
        float4 v0 = __ldg(r1 + c);
        float4 v1 = __ldg(r1 + c + 8);
        float w0 = __int_as_float(p0.y);
        float w1 = __int_as_float(p1.y);
        a0.x += w0 * u0.x; a0.y += w0 * u0.y; a0.z += w0 * u0.z; a0.w += w0 * u0.w;
        a1.x += w0 * u1.x; a1.y += w0 * u1.y; a1.z += w0 * u1.z; a1.w += w0 * u1.w;
        a0.x += w1 * v0.x; a0.y += w1 * v0.y; a0.z += w1 * v0.z; a0.w += w1 * v0.w;
        a1.x += w1 * v1.x; a1.y += w1 * v1.y; a1.z += w1 * v1.z; a1.w += w1 * v1.w;
    }
    if (i < deg) {
        int2 p0 = __ldg(bkt + i);
        const float4* r0 = (const float4*)(C + (size_t)p0.x * 128);
        float4 u0 = __ldg(r0 + c);
        float4 u1 = __ldg(r0 + c + 8);
        float w0 = __int_as_float(p0.y);
        a0.x += w0 * u0.x; a0.y += w0 * u0.y; a0.z += w0 * u0.z; a0.w += w0 * u0.w;
        a1.x += w0 * u1.x; a1.y += w0 * u1.y; a1.z += w0 * u1.z; a1.w += w0 * u1.w;
    }
    const float4* rp = (const float4*)(C + (size_t)node * 128) + 16;
    float4 rv0 = __ldg(rp + c);
    float4 rv1 = __ldg(rp + c + 8);
    a0.x += rv0.x; a0.y += rv0.y; a0.z += rv0.z; a0.w += rv0.w;
    a1.x += rv1.x; a1.y += rv1.y; a1.z += rv1.z; a1.w += rv1.w;
    if (do_relu) {
        a0.x = fmaxf(a0.x, 0.f); a0.y = fmaxf(a0.y, 0.f);
        a0.z = fmaxf(a0.z, 0.f); a0.w = fmaxf(a0.w, 0.f);
        a1.x = fmaxf(a1.x, 0.f); a1.y = fmaxf(a1.y, 0.f);
        a1.z = fmaxf(a1.z, 0.f); a1.w = fmaxf(a1.w, 0.f);
    }
    if (out32) {
        float4* op = (float4*)(out32 + (size_t)node * 64);
        op[c] = a0;
        op[c + 8] = a1;
    }
    if (split) {
        __half* sp = split + (size_t)node * 128;
        int f0 = 4 * c, f1 = 32 + 4 * c;
        __half hx = __float2half_rn(a0.x), hy = __float2half_rn(a0.y);
        __half hz = __float2half_rn(a0.z), hw = __float2half_rn(a0.w);
        *(__half2*)(sp + f0) = __halves2half2(hx, hy);
        *(__half2*)(sp + f0 + 2) = __halves2half2(hz, hw);
        *(__half2*)(sp + 64 + f0) = __halves2half2(
            __float2half_rn(a0.x - __half2float(hx)), __float2half_rn(a0.y - __half2float(hy)));
        *(__half2*)(sp + 64 + f0 + 2) = __halves2half2(
            __float2half_rn(a0.z - __half2float(hz)), __float2half_rn(a0.w - __half2float(hw)));
        hx = __float2half_rn(a1.x); hy = __float2half_rn(a1.y);
        hz = __float2half_rn(a1.z); hw = __float2half_rn(a1.w);
        *(__half2*)(sp + f1) = __halves2half2(hx, hy);
        *(__half2*)(sp + f1 + 2) = __halves2half2(hz, hw);
        *(__half2*)(sp + 64 + f1) = __halves2half2(
            __float2half_rn(a1.x - __half2float(hx)), __float2half_rn(a1.y - __half2float(hy)));
        *(__half2*)(sp + 64 + f1 + 2) = __halves2half2(
            __float2half_rn(a1.z - __half2float(hz)), __float2half_rn(a1.w - __half2float(hw)));
    }
}

// ---------------------------------------------------------------------------
// Decoder: pred[e] = relu(u[s]+v[d]) . dec_W2 + dec_b2 ; duplicated.
// ---------------------------------------------------------------------------
__global__ void decode_edges_h(const int* __restrict__ src, const int* __restrict__ dst,
                               const __half* __restrict__ uv,
                               const float* __restrict__ W2, const float* __restrict__ b2,
                               float* __restrict__ pred, int OBS) {
    int gt = blockIdx.x * blockDim.x + threadIdx.x;
    int e = gt >> 4;
    int c = gt & 15;
    if (e >= OBS) return;
    int s = src[e];
    int d = dst[e];
    uint4 ub = __ldg((const uint4*)(uv + (size_t)s * 256) + c);
    uint4 vb = __ldg((const uint4*)(uv + (size_t)d * 256 + 128) + c);
    float4 w0 = __ldg((const float4*)W2 + 2 * c);
    float4 w1 = __ldg((const float4*)W2 + 2 * c + 1);

    float2 fu0 = __half22float2(*(const half2*)&ub.x);
    float2 fu1 = __half22float2(*(const half2*)&ub.y);
    float2 fu2 = __half22float2(*(const half2*)&ub.z);
    float2 fu3 = __half22float2(*(const half2*)&ub.w);
    float2 fv0 = __half22float2(*(const half2*)&vb.x);
    float2 fv1 = __half22float2(*(const half2*)&vb.y);
    float2 fv2 = __half22float2(*(const half2*)&vb.z);
    float2 fv3 = __half22float2(*(const half2*)&vb.w);

    float acc = fmaxf(fu0.x + fv0.x, 0.f) * w0.x + fmaxf(fu0.y + fv0.y, 0.f) * w0.y
              + fmaxf(fu1.x + fv1.x, 0.f) * w0.z + fmaxf(fu1.y + fv1.y, 0.f) * w0.w
              + fmaxf(fu2.x + fv2.x, 0.f) * w1.x + fmaxf(fu2.y + fv2.y, 0.f) * w1.y
              + fmaxf(fu3.x + fv3.x, 0.f) * w1.z + fmaxf(fu3.y + fv3.y, 0.f) * w1.w;
#pragma unroll
    for (int o = 8; o > 0; o >>= 1) acc += __shfl_xor_sync(0xFFFFFFFFu, acc, o);
    if (c == 0) {
        float p = acc + __ldg(b2);
        pred[e] = p;
        pred[e + OBS] = p;
    }
}

// ---------------------------------------------------------------------------
// Launch
// ---------------------------------------------------------------------------
extern "C" void kernel_launch(void* const* d_in, const int* in_sizes, int n_in,
                              void* d_out, int out_size) {
    const float* x       = (const float*)d_in[0];
    const int*   ei      = (const int*)d_in[1];
    const float* ew      = (const float*)d_in[2];
    const float* W1_rel  = (const float*)d_in[4];
    const float* b1      = (const float*)d_in[5];
    const float* W1_root = (const float*)d_in[6];
    const float* W2_rel  = (const float*)d_in[7];
    const float* b2      = (const float*)d_in[8];
    const float* W2_root = (const float*)d_in[9];
    const float* W3_rel  = (const float*)d_in[10];
    const float* b3      = (const float*)d_in[11];
    const float* W3_root = (const float*)d_in[12];
    const float* dW1     = (const float*)d_in[13];
    const float* db1     = (const float*)d_in[14];
    const float* dW2     = (const float*)d_in[15];
    const float* db2     = (const float*)d_in[16];

    int N   = in_sizes[0] / 2;
    int E   = in_sizes[2];
    int OBS = E / 2;

    const int* src = ei;
    const int* dst = ei + E;

    float* out = (float*)d_out;
    float* z   = out + 2 * (size_t)OBS;

    float *C, *bias2, *bias3, *biasd;
    __half *h1s, *h2s, *zs, *uv, *ws2, *ws3, *wsd;
    int *cursor;
    int2* csr;
    cudaGetSymbolAddress((void**)&h1s,    g_h1s);
    cudaGetSymbolAddress((void**)&C,      g_C);
    cudaGetSymbolAddress((void**)&h2s,    g_h2s);
    cudaGetSymbolAddress((void**)&zs,     g_zs);
    cudaGetSymbolAddress((void**)&uv,     g_uv);
    cudaGetSymbolAddress((void**)&ws2,    g_ws2);
    cudaGetSymbolAddress((void**)&ws3,    g_ws3);
    cudaGetSymbolAddress((void**)&wsd,    g_wsd);
    cudaGetSymbolAddress((void**)&bias2,  g_bias2);
    cudaGetSymbolAddress((void**)&bias3,  g_bias3);
    cudaGetSymbolAddress((void**)&biasd,  g_biasd);
    cudaGetSymbolAddress((void**)&cursor, g_cursor);
    cudaGetSymbolAddress((void**)&csr,    g_csr);

    // dyn smem: 2 H bufs + 2 W bufs + bias tile (epilogue reuses base)
    const int SMEM = 2 * (128 * 40) * 2 + 2 * (32 * 72) * 2 + 16 * 64 * 4;  // 33792

    const int TB = 256;
    int eb = (E + TB - 1) / TB;
    int mb128 = (N + 127) / 128;

    // ---- prep (1 launch) ----
    {
        int total = 128 * 128 + 64 * 128 + 64 * 256 + 128 + 128 + 256;
        prep_all<<<(total + TB - 1) / TB, TB>>>(W2_rel, W2_root, W3_rel, W3_root, dW1,
                                                b2, b3, db1, ws2, ws3, wsd,
                                                bias2, bias3, biasd);
    }

    // ---- Bucketed CSR ----
    cudaMemsetAsync(cursor, 0, (size_t)N * sizeof(int));
    fill_kernel<<<eb, TB>>>(src, dst, ew, cursor, csr, E);

    // ---- Layer 1 fused ----
    layer1_fused<<<(N * 4 + TB - 1) / TB, TB>>>(csr, cursor, x, W1_rel, W1_root, b1, h1s, N);

    // ---- Layer 2: pipelined gemm (128->[y64|r64]) + fused gather ----
    {
        dim3 grid(mb128, 2);
        gemm_pipe<128, 128, float><<<grid, 256, SMEM>>>(h1s, ws2, bias2, C);
    }
    gather64<<<(N + 31) / 32, TB>>>(csr, cursor, C, nullptr, h2s, N, 1);

    // ---- Layer 3 ----
    {
        dim3 grid(mb128, 2);
        gemm_pipe<64, 128, float><<<grid, 256, SMEM>>>(h2s, ws3, bias3, C);
    }
    gather64<<<(N + 31) / 32, TB>>>(csr, cursor, C, z, zs, N, 0);

    // ---- Decoder ----
    {
        dim3 grid(mb128, 4);
        gemm_pipe<64, 256, __half><<<grid, 256, SMEM>>>(zs, wsd, biasd, uv);
    }
    decode_edges_h<<<((size_t)OBS * 16 + TB - 1) / TB, TB>>>(src, dst, uv, dW2, db2, out, OBS);
}

// round 7
// speedup vs baseline: 1.5496x; 1.0210x over previous
#include <cuda_runtime.h>
#include <cuda_fp16.h>
#include <mma.h>
#include <cstddef>
#include <cstdint>

using namespace nvcuda;

// ---------------------------------------------------------------------------
// Static scratch (padded to NPAD rows so gemm loads/stores are branch-free)
// ---------------------------------------------------------------------------
#define NMAX 50000
#define NPAD 50176
#define CAP  192

__device__ __half g_h1s[(size_t)NPAD * 256];   // layer1 out, split fp16 [hi128|lo128]
__device__ float  g_C[(size_t)NPAD * 128];     // gemm out [y64|r64] fp32
__device__ __half g_h2s[(size_t)NPAD * 128];   // h2 split [hi64|lo64]
__device__ __half g_zs[(size_t)NPAD * 128];    // z split  [hi64|lo64]
__device__ __half g_uv[(size_t)NPAD * 256];    // decoder [u128|v128] fp16

// split weights + biases
__device__ __half g_ws2[256 * 128];
__device__ __half g_ws3[128 * 128];
__device__ __half g_wsd[128 * 256];
__device__ float  g_bias2[128];
__device__ float  g_bias3[128];
__device__ float  g_biasd[256];

// bucketed CSR
__device__ int  g_cursor[NMAX];
__device__ int2 g_csr[(size_t)NMAX * CAP];

// ---------------------------------------------------------------------------
// cp.async helpers
// ---------------------------------------------------------------------------
__device__ __forceinline__ void cp16(void* smem, const void* gptr) {
    unsigned int s = (unsigned int)__cvta_generic_to_shared(smem);
    asm volatile("cp.async.ca.shared.global [%0], [%1], 16;\n" :: "r"(s), "l"(gptr));
}
__device__ __forceinline__ void cp_commit() {
    asm volatile("cp.async.commit_group;\n");
}
template <int n>
__device__ __forceinline__ void cp_wait() {
    asm volatile("cp.async.wait_group %0;\n" :: "n"(n));
}

// ---------------------------------------------------------------------------
// Single prep kernel: all weight splits + all biases
// ---------------------------------------------------------------------------
__global__ void prep_all(const float* __restrict__ W2_rel, const float* __restrict__ W2_root,
                         const float* __restrict__ W3_rel, const float* __restrict__ W3_root,
                         const float* __restrict__ dW1,
                         const float* __restrict__ b2, const float* __restrict__ b3,
                         const float* __restrict__ db1,
                         __half* __restrict__ ws2, __half* __restrict__ ws3,
                         __half* __restrict__ wsd,
                         float* __restrict__ bias2, float* __restrict__ bias3,
                         float* __restrict__ biasd) {
    int i = blockIdx.x * blockDim.x + threadIdx.x;
    const int A = 128 * 128;
    const int B = 64 * 128;
    const int Cc = 64 * 256;
    if (i < A) {
        int k = i >> 7, j = i & 127;
        float v = (j < 64) ? W2_rel[k * 64 + j] : W2_root[k * 64 + (j - 64)];
        __half hi = __float2half_rn(v);
        ws2[(size_t)k * 128 + j] = hi;
        ws2[(size_t)(128 + k) * 128 + j] = __float2half_rn(v - __half2float(hi));
        return;
    }
    i -= A;
    if (i < B) {
        int k = i >> 7, j = i & 127;
        float v = (j < 64) ? W3_rel[k * 64 + j] : W3_root[k * 64 + (j - 64)];
        __half hi = __float2half_rn(v);
        ws3[(size_t)k * 128 + j] = hi;
        ws3[(size_t)(64 + k) * 128 + j] = __float2half_rn(v - __half2float(hi));
        return;
    }
    i -= B;
    if (i < Cc) {
        int k = i >> 8, j = i & 255;
        float v = dW1[k * 128 + (j & 127) + ((j >> 7) ? 64 * 128 : 0)];
        __half hi = __float2half_rn(v);
        wsd[(size_t)k * 256 + j] = hi;
        wsd[(size_t)(64 + k) * 256 + j] = __float2half_rn(v - __half2float(hi));
        return;
    }
    i -= Cc;
    if (i < 128) { bias2[i] = (i >= 64) ? b2[i - 64] : 0.f; return; }
    i -= 128;
    if (i < 128) { bias3[i] = (i >= 64) ? b3[i - 64] : 0.f; return; }
    i -= 128;
    if (i < 256) { biasd[i] = (i < 128) ? db1[i] : 0.f; return; }
}

// ---------------------------------------------------------------------------
// Bucketed CSR fill
// ---------------------------------------------------------------------------
__global__ void fill_kernel(const int* __restrict__ src, const int* __restrict__ dst,
                            const float* __restrict__ ew, int* __restrict__ cursor,
                            int2* __restrict__ csr, int E) {
    int e = blockIdx.x * blockDim.x + threadIdx.x;
    if (e >= E) return;
    int d = dst[e];
    int p = atomicAdd(&cursor[d], 1);
    if (p < CAP) csr[(size_t)d * CAP + p] = make_int2(src[e], __float_as_int(ew[e]));
}

// ---------------------------------------------------------------------------
// Fused layer-1: quad-gather + expand to split fp16 (2 -> 128)
// ---------------------------------------------------------------------------
__global__ void layer1_fused(const int2* __restrict__ csr, const int* __restrict__ cnt,
                             const float* __restrict__ x,
                             const float* __restrict__ W1_rel,
                             const float* __restrict__ W1_root,
                             const float* __restrict__ b1,
                             __half* __restrict__ h1s, int N) {
    int tid = blockIdx.x * blockDim.x + threadIdx.x;
    int n = tid >> 2;
    int l = tid & 3;
    if (n >= N) return;
    int deg = __ldg(cnt + n);
    const int2* bkt = csr + (size_t)n * CAP;
    float a0 = 0.f, a1 = 0.f;
    for (int i = l; i < deg; i += 4) {
        int2 p = __ldg(bkt + i);
        float w = __int_as_float(p.y);
        float2 xv = __ldg((const float2*)(x + 2 * (size_t)p.x));
        a0 += w * xv.x;
        a1 += w * xv.y;
    }
#pragma unroll
    for (int o = 1; o < 4; o <<= 1) {
        a0 += __shfl_xor_sync(0xFFFFFFFFu, a0, o);
        a1 += __shfl_xor_sync(0xFFFFFFFFu, a1, o);
    }
    float2 xv = __ldg((const float2*)(x + 2 * (size_t)n));
    __half* hp = h1s + (size_t)n * 256;
#pragma unroll 4
    for (int j = 0; j < 16; j++) {
        int f = l * 32 + 2 * j;
        float v0 = a0 * __ldg(W1_rel + f) + a1 * __ldg(W1_rel + 128 + f)
                 + xv.x * __ldg(W1_root + f) + xv.y * __ldg(W1_root + 128 + f) + __ldg(b1 + f);
        float v1 = a0 * __ldg(W1_rel + f + 1) + a1 * __ldg(W1_rel + 129 + f)
                 + xv.x * __ldg(W1_root + f + 1) + xv.y * __ldg(W1_root + 129 + f) + __ldg(b1 + f + 1);
        v0 = fmaxf(v0, 0.f);
        v1 = fmaxf(v1, 0.f);
        __half h0 = __float2half_rn(v0), h1 = __float2half_rn(v1);
        *(__half2*)(hp + f) = __halves2half2(h0, h1);
        *(__half2*)(hp + 128 + f) = __halves2half2(
            __float2half_rn(v0 - __half2float(h0)), __float2half_rn(v1 - __half2float(h1)));
    }
}

// ---------------------------------------------------------------------------
// Pipelined split-fp16 wmma GEMM, wide N-tile.
//   M-tile 128, N-tile 128, K-tile 32, 8 warps @ 32x64 (acc 2x4).
// Hs: [NPAD x 2K] fp16 (hi cols [0,K), lo [K,2K)); Ws: [2K x OUT].
// 3 segments: (Hhi,Whi), (Hlo,Whi), (Hhi,Wlo). Bias preloaded into acc.
// fp32 out: direct fragment->global. fp16 out: two-pass smem convert.
// ---------------------------------------------------------------------------
template <int K, int OUT, typename TOut>
__global__ __launch_bounds__(256) void gemm_pipe(const __half* __restrict__ Hs,
                                                 const __half* __restrict__ Ws,
                                                 const float* __restrict__ bias,
                                                 TOut* __restrict__ C) {
    constexpr int K2 = 2 * K;
    constexpr int NKT = K / 32;
    constexpr int TOT = 3 * NKT;
    constexpr int LDH = 40;            // 32 + 8 pad (halves)
    constexpr int LDW = 136;           // 128 + 8 pad
    constexpr size_t HB = 128 * LDH;
    constexpr size_t WB = 32 * LDW;

    extern __shared__ char smem_raw[];
    __half* sh_h = (__half*)smem_raw;                               // [2][HB]
    __half* sh_w = (__half*)(smem_raw + 2 * HB * 2);                // [2][WB]
    float*  sh_b = (float*)(smem_raw + 2 * HB * 2 + 2 * WB * 2);    // 16*128
    float*  sh_c = (float*)smem_raw;                                // epilogue reuse (128x64)

    int m0 = blockIdx.x * 128;
    int n0 = blockIdx.y * 128;
    int t = threadIdx.x;      // 256
    int warp = t >> 5;
    int wm = (warp & 3) * 32;        // 4 m-tiles of 32
    int wn = (warp >> 2) * 64;       // 2 n-tiles of 64

    // bias tile: 16 rows x 128 cols, all rows identical (each thread: 8 floats)
    {
        int r = t >> 4, c8 = (t & 15) * 8;
        float4 b0 = *(const float4*)(bias + n0 + c8);
        float4 b1 = *(const float4*)(bias + n0 + c8 + 4);
        *(float4*)(sh_b + r * 128 + c8) = b0;
        *(float4*)(sh_b + r * 128 + c8 + 4) = b1;
    }

    auto load_step = [&](int step, int buf) {
        int seg = step / NKT, kt = step - seg * NKT;
        int hc = (seg == 1 ? K : 0) + kt * 32;
        int wr = (seg == 2 ? K : 0) + kt * 32;
        __half* hb = sh_h + buf * HB;
        __half* wb = sh_w + buf * WB;
        // H tile: 128 rows x 32 halves = 512 chunks of 16B
#pragma unroll
        for (int i = 0; i < 2; i++) {
            int idx = t + i * 256;
            int row = idx >> 2, ch = idx & 3;
            cp16(hb + row * LDH + ch * 8, Hs + (size_t)(m0 + row) * K2 + hc + ch * 8);
        }
        // W tile: 32 rows x 128 halves = 512 chunks of 16B
#pragma unroll
        for (int i = 0; i < 2; i++) {
            int idx = t + i * 256;
            int row = idx >> 4, ch = idx & 15;
            cp16(wb + row * LDW + ch * 8, Ws + (size_t)(wr + row) * OUT + n0 + ch * 8);
        }
    };

    load_step(0, 0);
    cp_commit();

    __syncthreads();  // bias tile visible
    wmma::fragment<wmma::accumulator, 16, 16, 16, float> acc[2][4];
#pragma unroll
    for (int i = 0; i < 2; i++)
#pragma unroll
        for (int j = 0; j < 4; j++)
            wmma::load_matrix_sync(acc[i][j], sh_b + wn + j * 16, 128, wmma::mem_row_major);

    for (int step = 0; step < TOT; step++) {
        int cur = step & 1;
        if (step + 1 < TOT) load_step(step + 1, cur ^ 1);
        cp_commit();
        cp_wait<1>();
        __syncthreads();
        const __half* hb = sh_h + cur * HB;
        const __half* wb = sh_w + cur * WB;
#pragma unroll
        for (int kk = 0; kk < 32; kk += 16) {
            wmma::fragment<wmma::matrix_a, 16, 16, 16, __half, wmma::row_major> a0, a1;
            wmma::fragment<wmma::matrix_b, 16, 16, 16, __half, wmma::row_major> b[4];
            wmma::load_matrix_sync(a0, hb + (wm + 0) * LDH + kk, LDH);
            wmma::load_matrix_sync(a1, hb + (wm + 16) * LDH + kk, LDH);
#pragma unroll
            for (int j = 0; j < 4; j++)
                wmma::load_matrix_sync(b[j], wb + kk * LDW + wn + j * 16, LDW);
#pragma unroll
            for (int j = 0; j < 4; j++) {
                wmma::mma_sync(acc[0][j], a0, b[j], acc[0][j]);
                wmma::mma_sync(acc[1][j], a1, b[j], acc[1][j]);
            }
        }
        __syncthreads();
    }

    if constexpr (sizeof(TOut) == 4) {
        // fp32: store fragments straight to global
#pragma unroll
        for (int i = 0; i < 2; i++)
#pragma unroll
            for (int j = 0; j < 4; j++)
                wmma::store_matrix_sync((float*)C + (size_t)(m0 + wm + i * 16) * OUT + n0 + wn + j * 16,
                                        acc[i][j], OUT, wmma::mem_row_major);
    } else {
        // fp16: two passes over the two 64-col warp groups through 128x64 smem
#pragma unroll
        for (int g = 0; g < 2; g++) {
            if ((warp >> 2) == g) {
#pragma unroll
                for (int i = 0; i < 2; i++)
#pragma unroll
                    for (int j = 0; j < 4; j++)
                        wmma::store_matrix_sync(sh_c + (size_t)(wm + i * 16) * 64 + j * 16,
                                                acc[i][j], 64, wmma::mem_row_major);
            }
            __syncthreads();
            for (int idx = t; idx < 128 * 64; idx += 256) {
                int row = idx >> 6, col = idx & 63;
                ((__half*)C)[(size_t)(m0 + row) * OUT + n0 + g * 64 + col] =
                    __float2half_rn(sh_c[idx]);
            }
            __syncthreads();
        }
    }
}

// ---------------------------------------------------------------------------
// Fused gather + residual + act. C holds [y64|r64] rows of 128 fp32.
// ---------------------------------------------------------------------------
__global__ void gather64(const int2* __restrict__ csr, const int* __restrict__ cnt,
                         const float* __restrict__ C, float* __restrict__ out32,
                         __half* __restrict__ split, int N, int do_relu) {
    int node = blockIdx.x * 32 + (threadIdx.x >> 3);
    int c = threadIdx.x & 7;
    if (node >= N) return;
    int deg = __ldg(cnt + node);
    const int2* bkt = csr + (size_t)node * CAP;
    float4 a0 = make_float4(0, 0, 0, 0);
    float4 a1 = make_float4(0, 0, 0, 0);
    int i = 0;
    for (; i + 2 <= deg; i += 2) {
        int2 p0 = __ldg(bkt + i);
        int2 p1 = __ldg(bkt + i + 1);
        const float4* r0 = (const float4*)(C + (size_t)p0.x * 128);
        const float4* r1 = (const float4*)(C + (size_t)p1.x * 128);
        float4 u0 = __ldg(r0 + c);
        float4 u1 = __ldg(r0 + c + 8);
        float4 v0 = __ldg(r1 + c);
        float4 v1 = __ldg(r1 + c + 8);
        float w0 = __int_as_float(p0.y);
        float w1 = __int_as_float(p1.y);
        a0.x += w0 * u0.x; a0.y += w0 * u0.y; a0.z += w0 * u0.z; a0.w += w0 * u0.w;
        a1.x += w0 * u1.x; a1.y += w0 * u1.y; a1.z += w0 * u1.z; a1.w += w0 * u1.w;
        a0.x += w1 * v0.x; a0.y += w1 * v0.y; a0.z += w1 * v0.z; a0.w += w1 * v0.w;
        a1.x += w1 * v1.x; a1.y += w1 * v1.y; a1.z += w1 * v1.z; a1.w += w1 * v1.w;
    }
    if (i < deg) {
        int2 p0 = __ldg(bkt + i);
        const float4* r0 = (const float4*)(C + (size_t)p0.x * 128);
        float4 u0 = __ldg(r0 + c);
        float4 u1 = __ldg(r0 + c + 8);
        float w0 = __int_as_float(p0.y);
        a0.x += w0 * u0.x; a0.y += w0 * u0.y; a0.z += w0 * u0.z; a0.w += w0 * u0.w;
        a1.x += w0 * u1.x; a1.y += w0 * u1.y; a1.z += w0 * u1.z; a1.w += w0 * u1.w;
    }
    const float4* rp = (const float4*)(C + (size_t)node * 128) + 16;
    float4 rv0 = __ldg(rp + c);
    float4 rv1 = __ldg(rp + c + 8);
    a0.x += rv0.x; a0.y += rv0.y; a0.z += rv0.z; a0.w += rv0.w;
    a1.x += rv1.x; a1.y += rv1.y; a1.z += rv1.z; a1.w += rv1.w;
    if (do_relu) {
        a0.x = fmaxf(a0.x, 0.f); a0.y = fmaxf(a0.y, 0.f);
        a0.z = fmaxf(a0.z, 0.f); a0.w = fmaxf(a0.w, 0.f);
        a1.x = fmaxf(a1.x, 0.f); a1.y = fmaxf(a1.y, 0.f);
        a1.z = fmaxf(a1.z, 0.f); a1.w = fmaxf(a1.w, 0.f);
    }
    if (out32) {
        float4* op = (float4*)(out32 + (size_t)node * 64);
        op[c] = a0;
        op[c + 8] = a1;
    }
    if (split) {
        __half* sp = split + (size_t)node * 128;
        int f0 = 4 * c, f1 = 32 + 4 * c;
        __half hx = __float2half_rn(a0.x), hy = __float2half_rn(a0.y);
        __half hz = __float2half_rn(a0.z), hw = __float2half_rn(a0.w);
        *(__half2*)(sp + f0) = __halves2half2(hx, hy);
        *(__half2*)(sp + f0 + 2) = __halves2half2(hz, hw);
        *(__half2*)(sp + 64 + f0) = __halves2half2(
            __float2half_rn(a0.x - __half2float(hx)), __float2half_rn(a0.y - __half2float(hy)));
        *(__half2*)(sp + 64 + f0 + 2) = __halves2half2(
            __float2half_rn(a0.z - __half2float(hz)), __float2half_rn(a0.w - __half2float(hw)));
        hx = __float2half_rn(a1.x); hy = __float2half_rn(a1.y);
        hz = __float2half_rn(a1.z); hw = __float2half_rn(a1.w);
        *(__half2*)(sp + f1) = __halves2half2(hx, hy);
        *(__half2*)(sp + f1 + 2) = __halves2half2(hz, hw);
        *(__half2*)(sp + 64 + f1) = __halves2half2(
            __float2half_rn(a1.x - __half2float(hx)), __float2half_rn(a1.y - __half2float(hy)));
        *(__half2*)(sp + 64 + f1 + 2) = __halves2half2(
            __float2half_rn(a1.z - __half2float(hz)), __float2half_rn(a1.w - __half2float(hw)));
    }
}

// ---------------------------------------------------------------------------
// Decoder: pred[e] = relu(u[s]+v[d]) . dec_W2 + dec_b2 ; duplicated.
// ---------------------------------------------------------------------------
__global__ void decode_edges_h(const int* __restrict__ src, const int* __restrict__ dst,
                               const __half* __restrict__ uv,
                               const float* __restrict__ W2, const float* __restrict__ b2,
                               float* __restrict__ pred, int OBS) {
    int gt = blockIdx.x * blockDim.x + threadIdx.x;
    int e = gt >> 4;
    int c = gt & 15;
    if (e >= OBS) return;
    int s = src[e];
    int d = dst[e];
    uint4 ub = __ldg((const uint4*)(uv + (size_t)s * 256) + c);
    uint4 vb = __ldg((const uint4*)(uv + (size_t)d * 256 + 128) + c);
    float4 w0 = __ldg((const float4*)W2 + 2 * c);
    float4 w1 = __ldg((const float4*)W2 + 2 * c + 1);

    float2 fu0 = __half22float2(*(const half2*)&ub.x);
    float2 fu1 = __half22float2(*(const half2*)&ub.y);
    float2 fu2 = __half22float2(*(const half2*)&ub.z);
    float2 fu3 = __half22float2(*(const half2*)&ub.w);
    float2 fv0 = __half22float2(*(const half2*)&vb.x);
    float2 fv1 = __half22float2(*(const half2*)&vb.y);
    float2 fv2 = __half22float2(*(const half2*)&vb.z);
    float2 fv3 = __half22float2(*(const half2*)&vb.w);

    float acc = fmaxf(fu0.x + fv0.x, 0.f) * w0.x + fmaxf(fu0.y + fv0.y, 0.f) * w0.y
              + fmaxf(fu1.x + fv1.x, 0.f) * w0.z + fmaxf(fu1.y + fv1.y, 0.f) * w0.w
              + fmaxf(fu2.x + fv2.x, 0.f) * w1.x + fmaxf(fu2.y + fv2.y, 0.f) * w1.y
              + fmaxf(fu3.x + fv3.x, 0.f) * w1.z + fmaxf(fu3.y + fv3.y, 0.f) * w1.w;
#pragma unroll
    for (int o = 8; o > 0; o >>= 1) acc += __shfl_xor_sync(0xFFFFFFFFu, acc, o);
    if (c == 0) {
        float p = acc + __ldg(b2);
        pred[e] = p;
        pred[e + OBS] = p;
    }
}

// ---------------------------------------------------------------------------
// Launch
// ---------------------------------------------------------------------------
extern "C" void kernel_launch(void* const* d_in, const int* in_sizes, int n_in,
                              void* d_out, int out_size) {
    const float* x       = (const float*)d_in[0];
    const int*   ei      = (const int*)d_in[1];
    const float* ew      = (const float*)d_in[2];
    const float* W1_rel  = (const float*)d_in[4];
    const float* b1      = (const float*)d_in[5];
    const float* W1_root = (const float*)d_in[6];
    const float* W2_rel  = (const float*)d_in[7];
    const float* b2      = (const float*)d_in[8];
    const float* W2_root = (const float*)d_in[9];
    const float* W3_rel  = (const float*)d_in[10];
    const float* b3      = (const float*)d_in[11];
    const float* W3_root = (const float*)d_in[12];
    const float* dW1     = (const float*)d_in[13];
    const float* db1     = (const float*)d_in[14];
    const float* dW2     = (const float*)d_in[15];
    const float* db2     = (const float*)d_in[16];

    int N   = in_sizes[0] / 2;
    int E   = in_sizes[2];
    int OBS = E / 2;

    const int* src = ei;
    const int* dst = ei + E;

    float* out = (float*)d_out;
    float* z   = out + 2 * (size_t)OBS;

    float *C, *bias2, *bias3, *biasd;
    __half *h1s, *h2s, *zs, *uv, *ws2, *ws3, *wsd;
    int *cursor;
    int2* csr;
    cudaGetSymbolAddress((void**)&h1s,    g_h1s);
    cudaGetSymbolAddress((void**)&C,      g_C);
    cudaGetSymbolAddress((void**)&h2s,    g_h2s);
    cudaGetSymbolAddress((void**)&zs,     g_zs);
    cudaGetSymbolAddress((void**)&uv,     g_uv);
    cudaGetSymbolAddress((void**)&ws2,    g_ws2);
    cudaGetSymbolAddress((void**)&ws3,    g_ws3);
    cudaGetSymbolAddress((void**)&wsd,    g_wsd);
    cudaGetSymbolAddress((void**)&bias2,  g_bias2);
    cudaGetSymbolAddress((void**)&bias3,  g_bias3);
    cudaGetSymbolAddress((void**)&biasd,  g_biasd);
    cudaGetSymbolAddress((void**)&cursor, g_cursor);
    cudaGetSymbolAddress((void**)&csr,    g_csr);

    // dyn smem: 2 H bufs + 2 W bufs + bias tile (epilogue reuses base)
    const int SMEM = 2 * (128 * 40) * 2 + 2 * (32 * 136) * 2 + 16 * 128 * 4;  // 46080

    const int TB = 256;
    int eb = (E + TB - 1) / TB;
    int mb128 = (N + 127) / 128;

    // ---- prep (1 launch) ----
    {
        int total = 128 * 128 + 64 * 128 + 64 * 256 + 128 + 128 + 256;
        prep_all<<<(total + TB - 1) / TB, TB>>>(W2_rel, W2_root, W3_rel, W3_root, dW1,
                                                b2, b3, db1, ws2, ws3, wsd,
                                                bias2, bias3, biasd);
    }

    // ---- Bucketed CSR ----
    cudaMemsetAsync(cursor, 0, (size_t)N * sizeof(int));
    fill_kernel<<<eb, TB>>>(src, dst, ew, cursor, csr, E);

    // ---- Layer 1 fused ----
    layer1_fused<<<(N * 4 + TB - 1) / TB, TB>>>(csr, cursor, x, W1_rel, W1_root, b1, h1s, N);

    // ---- Layer 2: pipelined gemm (128->[y64|r64]) + fused gather ----
    gemm_pipe<128, 128, float><<<dim3(mb128, 1), 256, SMEM>>>(h1s, ws2, bias2, C);
    gather64<<<(N + 31) / 32, TB>>>(csr, cursor, C, nullptr, h2s, N, 1);

    // ---- Layer 3 ----
    gemm_pipe<64, 128, float><<<dim3(mb128, 1), 256, SMEM>>>(h2s, ws3, bias3, C);
    gather64<<<(N + 31) / 32, TB>>>(csr, cursor, C, z, zs, N, 0);

    // ---- Decoder ----
    gemm_pipe<64, 256, __half><<<dim3(mb128, 2), 256, SMEM>>>(zs, wsd, biasd, uv);
    decode_edges_h<<<((size_t)OBS * 16 + TB - 1) / TB, TB>>>(src, dst, uv, dW2, db2, out, OBS);
}

// round 8
// speedup vs baseline: 1.6032x; 1.0346x over previous
#include <cuda_runtime.h>
#include <cuda_fp16.h>
#include <mma.h>
#include <cstddef>
#include <cstdint>

using namespace nvcuda;

// ---------------------------------------------------------------------------
// Static scratch (padded to NPAD rows so gemm loads/stores are branch-free)
// ---------------------------------------------------------------------------
#define NMAX 50000
#define NPAD 50176
#define CAP  192

__device__ __half g_h1s[(size_t)NPAD * 256];   // layer1 out, split fp16 [hi128|lo128]
__device__ __half g_y16[(size_t)NPAD * 64];    // gemm message out y, fp16
__device__ float  g_r32[(size_t)NPAD * 64];    // gemm residual out r, fp32
__device__ __half g_h2s[(size_t)NPAD * 128];   // h2 split [hi64|lo64]
__device__ __half g_zs[(size_t)NPAD * 128];    // z split  [hi64|lo64]
__device__ __half g_uv[(size_t)NPAD * 256];    // decoder [u128|v128] fp16

// split weights + biases
__device__ __half g_ws2[256 * 128];
__device__ __half g_ws3[128 * 128];
__device__ __half g_wsd[128 * 256];
__device__ float  g_bias2[128];
__device__ float  g_bias3[128];
__device__ float  g_biasd[256];

// bucketed CSR
__device__ int  g_cursor[NMAX];
__device__ int2 g_csr[(size_t)NMAX * CAP];

// ---------------------------------------------------------------------------
// cp.async helpers
// ---------------------------------------------------------------------------
__device__ __forceinline__ void cp16(void* smem, const void* gptr) {
    unsigned int s = (unsigned int)__cvta_generic_to_shared(smem);
    asm volatile("cp.async.ca.shared.global [%0], [%1], 16;\n" :: "r"(s), "l"(gptr));
}
__device__ __forceinline__ void cp_commit() {
    asm volatile("cp.async.commit_group;\n");
}
template <int n>
__device__ __forceinline__ void cp_wait() {
    asm volatile("cp.async.wait_group %0;\n" :: "n"(n));
}

// ---------------------------------------------------------------------------
// Single prep kernel: all weight splits + all biases
// ---------------------------------------------------------------------------
__global__ void prep_all(const float* __restrict__ W2_rel, const float* __restrict__ W2_root,
                         const float* __restrict__ W3_rel, const float* __restrict__ W3_root,
                         const float* __restrict__ dW1,
                         const float* __restrict__ b2, const float* __restrict__ b3,
                         const float* __restrict__ db1,
                         __half* __restrict__ ws2, __half* __restrict__ ws3,
                         __half* __restrict__ wsd,
                         float* __restrict__ bias2, float* __restrict__ bias3,
                         float* __restrict__ biasd) {
    int i = blockIdx.x * blockDim.x + threadIdx.x;
    const int A = 128 * 128;
    const int B = 64 * 128;
    const int Cc = 64 * 256;
    if (i < A) {
        int k = i >> 7, j = i & 127;
        float v = (j < 64) ? W2_rel[k * 64 + j] : W2_root[k * 64 + (j - 64)];
        __half hi = __float2half_rn(v);
        ws2[(size_t)k * 128 + j] = hi;
        ws2[(size_t)(128 + k) * 128 + j] = __float2half_rn(v - __half2float(hi));
        return;
    }
    i -= A;
    if (i < B) {
        int k = i >> 7, j = i & 127;
        float v = (j < 64) ? W3_rel[k * 64 + j] : W3_root[k * 64 + (j - 64)];
        __half hi = __float2half_rn(v);
        ws3[(size_t)k * 128 + j] = hi;
        ws3[(size_t)(64 + k) * 128 + j] = __float2half_rn(v - __half2float(hi));
        return;
    }
    i -= B;
    if (i < Cc) {
        int k = i >> 8, j = i & 255;
        float v = dW1[k * 128 + (j & 127) + ((j >> 7) ? 64 * 128 : 0)];
        __half hi = __float2half_rn(v);
        wsd[(size_t)k * 256 + j] = hi;
        wsd[(size_t)(64 + k) * 256 + j] = __float2half_rn(v - __half2float(hi));
        return;
    }
    i -= Cc;
    if (i < 128) { bias2[i] = (i >= 64) ? b2[i - 64] : 0.f; return; }
    i -= 128;
    if (i < 128) { bias3[i] = (i >= 64) ? b3[i - 64] : 0.f; return; }
    i -= 128;
    if (i < 256) { biasd[i] = (i < 128) ? db1[i] : 0.f; return; }
}

// ---------------------------------------------------------------------------
// Bucketed CSR fill
// ---------------------------------------------------------------------------
__global__ void fill_kernel(const int* __restrict__ src, const int* __restrict__ dst,
                            const float* __restrict__ ew, int* __restrict__ cursor,
                            int2* __restrict__ csr, int E) {
    int e = blockIdx.x * blockDim.x + threadIdx.x;
    if (e >= E) return;
    int d = dst[e];
    int p = atomicAdd(&cursor[d], 1);
    if (p < CAP) csr[(size_t)d * CAP + p] = make_int2(src[e], __float_as_int(ew[e]));
}

// ---------------------------------------------------------------------------
// Fused layer-1: quad-gather + expand to split fp16 (2 -> 128)
// ---------------------------------------------------------------------------
__global__ void layer1_fused(const int2* __restrict__ csr, const int* __restrict__ cnt,
                             const float* __restrict__ x,
                             const float* __restrict__ W1_rel,
                             const float* __restrict__ W1_root,
                             const float* __restrict__ b1,
                             __half* __restrict__ h1s, int N) {
    int tid = blockIdx.x * blockDim.x + threadIdx.x;
    int n = tid >> 2;
    int l = tid & 3;
    if (n >= N) return;
    int deg = __ldg(cnt + n);
    const int2* bkt = csr + (size_t)n * CAP;
    float a0 = 0.f, a1 = 0.f;
    for (int i = l; i < deg; i += 4) {
        int2 p = __ldg(bkt + i);
        float w = __int_as_float(p.y);
        float2 xv = __ldg((const float2*)(x + 2 * (size_t)p.x));
        a0 += w * xv.x;
        a1 += w * xv.y;
    }
#pragma unroll
    for (int o = 1; o < 4; o <<= 1) {
        a0 += __shfl_xor_sync(0xFFFFFFFFu, a0, o);
        a1 += __shfl_xor_sync(0xFFFFFFFFu, a1, o);
    }
    float2 xv = __ldg((const float2*)(x + 2 * (size_t)n));
    __half* hp = h1s + (size_t)n * 256;
#pragma unroll 4
    for (int j = 0; j < 16; j++) {
        int f = l * 32 + 2 * j;
        float v0 = a0 * __ldg(W1_rel + f) + a1 * __ldg(W1_rel + 128 + f)
                 + xv.x * __ldg(W1_root + f) + xv.y * __ldg(W1_root + 128 + f) + __ldg(b1 + f);
        float v1 = a0 * __ldg(W1_rel + f + 1) + a1 * __ldg(W1_rel + 129 + f)
                 + xv.x * __ldg(W1_root + f + 1) + xv.y * __ldg(W1_root + 129 + f) + __ldg(b1 + f + 1);
        v0 = fmaxf(v0, 0.f);
        v1 = fmaxf(v1, 0.f);
        __half h0 = __float2half_rn(v0), h1 = __float2half_rn(v1);
        *(__half2*)(hp + f) = __halves2half2(h0, h1);
        *(__half2*)(hp + 128 + f) = __halves2half2(
            __float2half_rn(v0 - __half2float(h0)), __float2half_rn(v1 - __half2float(h1)));
    }
}

// ---------------------------------------------------------------------------
// Pipelined split-fp16 wmma GEMM, wide N-tile.
//   M-tile 128, N-tile 128, K-tile 32, 8 warps @ 32x64 (acc 2x4).
// MODE 1: cols [0,64) -> fp16 Cy (y messages), cols [64,128) -> fp32 Cr.
// MODE 2: all OUT cols -> fp16 Cy (two-pass smem convert).
// ---------------------------------------------------------------------------
template <int K, int OUT, int MODE>
__global__ __launch_bounds__(256) void gemm_pipe(const __half* __restrict__ Hs,
                                                 const __half* __restrict__ Ws,
                                                 const float* __restrict__ bias,
                                                 __half* __restrict__ Cy,
                                                 float* __restrict__ Cr) {
    constexpr int K2 = 2 * K;
    constexpr int NKT = K / 32;
    constexpr int TOT = 3 * NKT;
    constexpr int LDH = 40;            // 32 + 8 pad (halves)
    constexpr int LDW = 136;           // 128 + 8 pad
    constexpr size_t HB = 128 * LDH;
    constexpr size_t WB = 32 * LDW;

    extern __shared__ char smem_raw[];
    __half* sh_h = (__half*)smem_raw;                               // [2][HB]
    __half* sh_w = (__half*)(smem_raw + 2 * HB * 2);                // [2][WB]
    float*  sh_b = (float*)(smem_raw + 2 * HB * 2 + 2 * WB * 2);    // 16*128
    float*  sh_c = (float*)smem_raw;                                // epilogue reuse (128x64)

    int m0 = blockIdx.x * 128;
    int n0 = blockIdx.y * 128;
    int t = threadIdx.x;      // 256
    int warp = t >> 5;
    int wm = (warp & 3) * 32;        // 4 m-tiles of 32
    int wn = (warp >> 2) * 64;       // 2 n-tiles of 64

    // bias tile: 16 rows x 128 cols, all rows identical (each thread: 8 floats)
    {
        int r = t >> 4, c8 = (t & 15) * 8;
        float4 b0 = *(const float4*)(bias + n0 + c8);
        float4 b1 = *(const float4*)(bias + n0 + c8 + 4);
        *(float4*)(sh_b + r * 128 + c8) = b0;
        *(float4*)(sh_b + r * 128 + c8 + 4) = b1;
    }

    auto load_step = [&](int step, int buf) {
        int seg = step / NKT, kt = step - seg * NKT;
        int hc = (seg == 1 ? K : 0) + kt * 32;
        int wr = (seg == 2 ? K : 0) + kt * 32;
        __half* hb = sh_h + buf * HB;
        __half* wb = sh_w + buf * WB;
#pragma unroll
        for (int i = 0; i < 2; i++) {
            int idx = t + i * 256;
            int row = idx >> 2, ch = idx & 3;
            cp16(hb + row * LDH + ch * 8, Hs + (size_t)(m0 + row) * K2 + hc + ch * 8);
        }
#pragma unroll
        for (int i = 0; i < 2; i++) {
            int idx = t + i * 256;
            int row = idx >> 4, ch = idx & 15;
            cp16(wb + row * LDW + ch * 8, Ws + (size_t)(wr + row) * OUT + n0 + ch * 8);
        }
    };

    load_step(0, 0);
    cp_commit();

    __syncthreads();  // bias tile visible
    wmma::fragment<wmma::accumulator, 16, 16, 16, float> acc[2][4];
#pragma unroll
    for (int i = 0; i < 2; i++)
#pragma unroll
        for (int j = 0; j < 4; j++)
            wmma::load_matrix_sync(acc[i][j], sh_b + wn + j * 16, 128, wmma::mem_row_major);

    for (int step = 0; step < TOT; step++) {
        int cur = step & 1;
        if (step + 1 < TOT) load_step(step + 1, cur ^ 1);
        cp_commit();
        cp_wait<1>();
        __syncthreads();
        const __half* hb = sh_h + cur * HB;
        const __half* wb = sh_w + cur * WB;
#pragma unroll
        for (int kk = 0; kk < 32; kk += 16) {
            wmma::fragment<wmma::matrix_a, 16, 16, 16, __half, wmma::row_major> a0, a1;
            wmma::fragment<wmma::matrix_b, 16, 16, 16, __half, wmma::row_major> b[4];
            wmma::load_matrix_sync(a0, hb + (wm + 0) * LDH + kk, LDH);
            wmma::load_matrix_sync(a1, hb + (wm + 16) * LDH + kk, LDH);
#pragma unroll
            for (int j = 0; j < 4; j++)
                wmma::load_matrix_sync(b[j], wb + kk * LDW + wn + j * 16, LDW);
#pragma unroll
            for (int j = 0; j < 4; j++) {
                wmma::mma_sync(acc[0][j], a0, b[j], acc[0][j]);
                wmma::mma_sync(acc[1][j], a1, b[j], acc[1][j]);
            }
        }
        __syncthreads();
    }

    if constexpr (MODE == 1) {
        // Warps 0-3 (wn==0, cols 0-63 = y): stage in smem, convert to fp16.
        // Warps 4-7 (wn==64, cols 64-127 = r): direct fp32 store (stride 64).
        if (wn == 0) {
#pragma unroll
            for (int i = 0; i < 2; i++)
#pragma unroll
                for (int j = 0; j < 4; j++)
                    wmma::store_matrix_sync(sh_c + (size_t)(wm + i * 16) * 64 + j * 16,
                                            acc[i][j], 64, wmma::mem_row_major);
        } else {
#pragma unroll
            for (int i = 0; i < 2; i++)
#pragma unroll
                for (int j = 0; j < 4; j++)
                    wmma::store_matrix_sync(Cr + (size_t)(m0 + wm + i * 16) * 64 + j * 16,
                                            acc[i][j], 64, wmma::mem_row_major);
        }
        __syncthreads();
        // convert 128x64 fp32 smem -> fp16 Cy (half2 stores)
        for (int idx = t; idx < 128 * 32; idx += 256) {
            int row = idx >> 5, cp = (idx & 31) * 2;
            float2 v = *(const float2*)(sh_c + (size_t)row * 64 + cp);
            *(__half2*)(Cy + (size_t)(m0 + row) * 64 + cp) =
                __halves2half2(__float2half_rn(v.x), __float2half_rn(v.y));
        }
    } else {
        // MODE 2: all cols fp16, two passes over the two 64-col warp groups
#pragma unroll
        for (int g = 0; g < 2; g++) {
            if ((warp >> 2) == g) {
#pragma unroll
                for (int i = 0; i < 2; i++)
#pragma unroll
                    for (int j = 0; j < 4; j++)
                        wmma::store_matrix_sync(sh_c + (size_t)(wm + i * 16) * 64 + j * 16,
                                                acc[i][j], 64, wmma::mem_row_major);
            }
            __syncthreads();
            for (int idx = t; idx < 128 * 64; idx += 256) {
                int row = idx >> 6, col = idx & 63;
                Cy[(size_t)(m0 + row) * OUT + n0 + g * 64 + col] = __float2half_rn(sh_c[idx]);
            }
            __syncthreads();
        }
    }
}

// ---------------------------------------------------------------------------
// Fused gather + residual + act. y16: fp16 messages [NPAD x 64];
// r32: fp32 residual [NPAD x 64]. 8 lanes/node, lane owns 8 feats.
// ---------------------------------------------------------------------------
__global__ void gather64(const int2* __restrict__ csr, const int* __restrict__ cnt,
                         const __half* __restrict__ y16, const float* __restrict__ r32,
                         float* __restrict__ out32, __half* __restrict__ split,
                         int N, int do_relu) {
    int node = blockIdx.x * 32 + (threadIdx.x >> 3);
    int c = threadIdx.x & 7;
    if (node >= N) return;
    int deg = __ldg(cnt + node);
    const int2* bkt = csr + (size_t)node * CAP;
    float4 a0 = make_float4(0, 0, 0, 0);
    float4 a1 = make_float4(0, 0, 0, 0);

    auto accum = [&](int2 p) {
        float w = __int_as_float(p.y);
        uint4 hv = __ldg((const uint4*)(y16 + (size_t)p.x * 64) + c);
        float2 f0 = __half22float2(*(const half2*)&hv.x);
        float2 f1 = __half22float2(*(const half2*)&hv.y);
        float2 f2 = __half22float2(*(const half2*)&hv.z);
        float2 f3 = __half22float2(*(const half2*)&hv.w);
        a0.x += w * f0.x; a0.y += w * f0.y; a0.z += w * f1.x; a0.w += w * f1.y;
        a1.x += w * f2.x; a1.y += w * f2.y; a1.z += w * f3.x; a1.w += w * f3.y;
    };

    int i = 0;
    for (; i + 2 <= deg; i += 2) {
        int2 p0 = __ldg(bkt + i);
        int2 p1 = __ldg(bkt + i + 1);
        accum(p0);
        accum(p1);
    }
    if (i < deg) accum(__ldg(bkt + i));

    // residual: lane owns feats [8c, 8c+8)
    const float4* rp = (const float4*)(r32 + (size_t)node * 64);
    float4 rv0 = __ldg(rp + 2 * c);
    float4 rv1 = __ldg(rp + 2 * c + 1);
    a0.x += rv0.x; a0.y += rv0.y; a0.z += rv0.z; a0.w += rv0.w;
    a1.x += rv1.x; a1.y += rv1.y; a1.z += rv1.z; a1.w += rv1.w;
    if (do_relu) {
        a0.x = fmaxf(a0.x, 0.f); a0.y = fmaxf(a0.y, 0.f);
        a0.z = fmaxf(a0.z, 0.f); a0.w = fmaxf(a0.w, 0.f);
        a1.x = fmaxf(a1.x, 0.f); a1.y = fmaxf(a1.y, 0.f);
        a1.z = fmaxf(a1.z, 0.f); a1.w = fmaxf(a1.w, 0.f);
    }
    if (out32) {
        float4* op = (float4*)(out32 + (size_t)node * 64);
        op[2 * c] = a0;
        op[2 * c + 1] = a1;
    }
    if (split) {
        // lane owns feats f = 8c .. 8c+7 (contiguous)
        __half* sp = split + (size_t)node * 128;
        int f = 8 * c;
        __half h0 = __float2half_rn(a0.x), h1 = __float2half_rn(a0.y);
        __half h2 = __float2half_rn(a0.z), h3 = __float2half_rn(a0.w);
        __half h4 = __float2half_rn(a1.x), h5 = __float2half_rn(a1.y);
        __half h6 = __float2half_rn(a1.z), h7 = __float2half_rn(a1.w);
        *(__half2*)(sp + f + 0) = __halves2half2(h0, h1);
        *(__half2*)(sp + f + 2) = __halves2half2(h2, h3);
        *(__half2*)(sp + f + 4) = __halves2half2(h4, h5);
        *(__half2*)(sp + f + 6) = __halves2half2(h6, h7);
        *(__half2*)(sp + 64 + f + 0) = __halves2half2(
            __float2half_rn(a0.x - __half2float(h0)), __float2half_rn(a0.y - __half2float(h1)));
        *(__half2*)(sp + 64 + f + 2) = __halves2half2(
            __float2half_rn(a0.z - __half2float(h2)), __float2half_rn(a0.w - __half2float(h3)));
        *(__half2*)(sp + 64 + f + 4) = __halves2half2(
            __float2half_rn(a1.x - __half2float(h4)), __float2half_rn(a1.y - __half2float(h5)));
        *(__half2*)(sp + 64 + f + 6) = __halves2half2(
            __float2half_rn(a1.z - __half2float(h6)), __float2half_rn(a1.w - __half2float(h7)));
    }
}

// ---------------------------------------------------------------------------
// Decoder: pred[e] = relu(u[s]+v[d]) . dec_W2 + dec_b2 ; duplicated.
// ---------------------------------------------------------------------------
__global__ void decode_edges_h(const int* __restrict__ src, const int* __restrict__ dst,
                               const __half* __restrict__ uv,
                               const float* __restrict__ W2, const float* __restrict__ b2,
                               float* __restrict__ pred, int OBS) {
    int gt = blockIdx.x * blockDim.x + threadIdx.x;
    int e = gt >> 4;
    int c = gt & 15;
    if (e >= OBS) return;
    int s = src[e];
    int d = dst[e];
    uint4 ub = __ldg((const uint4*)(uv + (size_t)s * 256) + c);
    uint4 vb = __ldg((const uint4*)(uv + (size_t)d * 256 + 128) + c);
    float4 w0 = __ldg((const float4*)W2 + 2 * c);
    float4 w1 = __ldg((const float4*)W2 + 2 * c + 1);

    float2 fu0 = __half22float2(*(const half2*)&ub.x);
    float2 fu1 = __half22float2(*(const half2*)&ub.y);
    float2 fu2 = __half22float2(*(const half2*)&ub.z);
    float2 fu3 = __half22float2(*(const half2*)&ub.w);
    float2 fv0 = __half22float2(*(const half2*)&vb.x);
    float2 fv1 = __half22float2(*(const half2*)&vb.y);
    float2 fv2 = __half22float2(*(const half2*)&vb.z);
    float2 fv3 = __half22float2(*(const half2*)&vb.w);

    float acc = fmaxf(fu0.x + fv0.x, 0.f) * w0.x + fmaxf(fu0.y + fv0.y, 0.f) * w0.y
              + fmaxf(fu1.x + fv1.x, 0.f) * w0.z + fmaxf(fu1.y + fv1.y, 0.f) * w0.w
              + fmaxf(fu2.x + fv2.x, 0.f) * w1.x + fmaxf(fu2.y + fv2.y, 0.f) * w1.y
              + fmaxf(fu3.x + fv3.x, 0.f) * w1.z + fmaxf(fu3.y + fv3.y, 0.f) * w1.w;
#pragma unroll
    for (int o = 8; o > 0; o >>= 1) acc += __shfl_xor_sync(0xFFFFFFFFu, acc, o);
    if (c == 0) {
        float p = acc + __ldg(b2);
        pred[e] = p;
        pred[e + OBS] = p;
    }
}

// ---------------------------------------------------------------------------
// Launch
// ---------------------------------------------------------------------------
extern "C" void kernel_launch(void* const* d_in, const int* in_sizes, int n_in,
                              void* d_out, int out_size) {
    const float* x       = (const float*)d_in[0];
    const int*   ei      = (const int*)d_in[1];
    const float* ew      = (const float*)d_in[2];
    const float* W1_rel  = (const float*)d_in[4];
    const float* b1      = (const float*)d_in[5];
    const float* W1_root = (const float*)d_in[6];
    const float* W2_rel  = (const float*)d_in[7];
    const float* b2      = (const float*)d_in[8];
    const float* W2_root = (const float*)d_in[9];
    const float* W3_rel  = (const float*)d_in[10];
    const float* b3      = (const float*)d_in[11];
    const float* W3_root = (const float*)d_in[12];
    const float* dW1     = (const float*)d_in[13];
    const float* db1     = (const float*)d_in[14];
    const float* dW2     = (const float*)d_in[15];
    const float* db2     = (const float*)d_in[16];

    int N   = in_sizes[0] / 2;
    int E   = in_sizes[2];
    int OBS = E / 2;

    const int* src = ei;
    const int* dst = ei + E;

    float* out = (float*)d_out;
    float* z   = out + 2 * (size_t)OBS;

    float *r32, *bias2, *bias3, *biasd;
    __half *h1s, *y16, *h2s, *zs, *uv, *ws2, *ws3, *wsd;
    int *cursor;
    int2* csr;
    cudaGetSymbolAddress((void**)&h1s,    g_h1s);
    cudaGetSymbolAddress((void**)&y16,    g_y16);
    cudaGetSymbolAddress((void**)&r32,    g_r32);
    cudaGetSymbolAddress((void**)&h2s,    g_h2s);
    cudaGetSymbolAddress((void**)&zs,     g_zs);
    cudaGetSymbolAddress((void**)&uv,     g_uv);
    cudaGetSymbolAddress((void**)&ws2,    g_ws2);
    cudaGetSymbolAddress((void**)&ws3,    g_ws3);
    cudaGetSymbolAddress((void**)&wsd,    g_wsd);
    cudaGetSymbolAddress((void**)&bias2,  g_bias2);
    cudaGetSymbolAddress((void**)&bias3,  g_bias3);
    cudaGetSymbolAddress((void**)&biasd,  g_biasd);
    cudaGetSymbolAddress((void**)&cursor, g_cursor);
    cudaGetSymbolAddress((void**)&csr,    g_csr);

    // dyn smem: 2 H bufs + 2 W bufs + bias tile (epilogue reuses base)
    const int SMEM = 2 * (128 * 40) * 2 + 2 * (32 * 136) * 2 + 16 * 128 * 4;  // 46080

    const int TB = 256;
    int eb = (E + TB - 1) / TB;
    int mb128 = (N + 127) / 128;

    // ---- prep (1 launch) ----
    {
        int total = 128 * 128 + 64 * 128 + 64 * 256 + 128 + 128 + 256;
        prep_all<<<(total + TB - 1) / TB, TB>>>(W2_rel, W2_root, W3_rel, W3_root, dW1,
                                                b2, b3, db1, ws2, ws3, wsd,
                                                bias2, bias3, biasd);
    }

    // ---- Bucketed CSR ----
    cudaMemsetAsync(cursor, 0, (size_t)N * sizeof(int));
    fill_kernel<<<eb, TB>>>(src, dst, ew, cursor, csr, E);

    // ---- Layer 1 fused ----
    layer1_fused<<<(N * 4 + TB - 1) / TB, TB>>>(csr, cursor, x, W1_rel, W1_root, b1, h1s, N);

    // ---- Layer 2: mixed-output gemm (y fp16 | r fp32) + fused gather ----
    gemm_pipe<128, 128, 1><<<dim3(mb128, 1), 256, SMEM>>>(h1s, ws2, bias2, y16, r32);
    gather64<<<(N + 31) / 32, TB>>>(csr, cursor, y16, r32, nullptr, h2s, N, 1);

    // ---- Layer 3 ----
    gemm_pipe<64, 128, 1><<<dim3(mb128, 1), 256, SMEM>>>(h2s, ws3, bias3, y16, r32);
    gather64<<<(N + 31) / 32, TB>>>(csr, cursor, y16, r32, z, zs, N, 0);

    // ---- Decoder ----
    gemm_pipe<64, 256, 2><<<dim3(mb128, 2), 256, SMEM>>>(zs, wsd, biasd, uv, nullptr);
    decode_edges_h<<<((size_t)OBS * 16 + TB - 1) / TB, TB>>>(src, dst, uv, dW2, db2, out, OBS);
}

// round 9
// speedup vs baseline: 1.8101x; 1.1291x over previous
#include <cuda_runtime.h>
#include <cuda_fp16.h>
#include <mma.h>
#include <cstddef>
#include <cstdint>

using namespace nvcuda;

// ---------------------------------------------------------------------------
// Static scratch (padded to NPAD rows so gemm loads/stores are branch-free)
// ---------------------------------------------------------------------------
#define NMAX 50000
#define NPAD 50176
#define CAP  192

__device__ __half g_h1[(size_t)NPAD * 128];    // layer1 out, fp16
__device__ __half g_y16[(size_t)NPAD * 64];    // gemm message out y, fp16
__device__ float  g_r32[(size_t)NPAD * 64];    // gemm residual out r, fp32
__device__ __half g_h2[(size_t)NPAD * 64];     // h2 fp16
__device__ __half g_z16[(size_t)NPAD * 64];    // z fp16 (decoder input)
__device__ __half g_uv[(size_t)NPAD * 256];    // decoder [u128|v128] fp16

// split weights (hi rows [0,K), lo rows [K,2K)) + padded biases
__device__ __half g_ws2[256 * 128];
__device__ __half g_ws3[128 * 128];
__device__ __half g_wsd[128 * 256];
__device__ float  g_bias2[128];
__device__ float  g_bias3[128];
__device__ float  g_biasd[256];

// bucketed CSR
__device__ int  g_cursor[NMAX];
__device__ int2 g_csr[(size_t)NMAX * CAP];

// ---------------------------------------------------------------------------
// cp.async helpers
// ---------------------------------------------------------------------------
__device__ __forceinline__ void cp16(void* smem, const void* gptr) {
    unsigned int s = (unsigned int)__cvta_generic_to_shared(smem);
    asm volatile("cp.async.ca.shared.global [%0], [%1], 16;\n" :: "r"(s), "l"(gptr));
}
__device__ __forceinline__ void cp_commit() {
    asm volatile("cp.async.commit_group;\n");
}
template <int n>
__device__ __forceinline__ void cp_wait() {
    asm volatile("cp.async.wait_group %0;\n" :: "n"(n));
}

// ---------------------------------------------------------------------------
// Single prep kernel: all weight splits + all biases
// ---------------------------------------------------------------------------
__global__ void prep_all(const float* __restrict__ W2_rel, const float* __restrict__ W2_root,
                         const float* __restrict__ W3_rel, const float* __restrict__ W3_root,
                         const float* __restrict__ dW1,
                         const float* __restrict__ b2, const float* __restrict__ b3,
                         const float* __restrict__ db1,
                         __half* __restrict__ ws2, __half* __restrict__ ws3,
                         __half* __restrict__ wsd,
                         float* __restrict__ bias2, float* __restrict__ bias3,
                         float* __restrict__ biasd) {
    int i = blockIdx.x * blockDim.x + threadIdx.x;
    const int A = 128 * 128;
    const int B = 64 * 128;
    const int Cc = 64 * 256;
    if (i < A) {
        int k = i >> 7, j = i & 127;
        float v = (j < 64) ? W2_rel[k * 64 + j] : W2_root[k * 64 + (j - 64)];
        __half hi = __float2half_rn(v);
        ws2[(size_t)k * 128 + j] = hi;
        ws2[(size_t)(128 + k) * 128 + j] = __float2half_rn(v - __half2float(hi));
        return;
    }
    i -= A;
    if (i < B) {
        int k = i >> 7, j = i & 127;
        float v = (j < 64) ? W3_rel[k * 64 + j] : W3_root[k * 64 + (j - 64)];
        __half hi = __float2half_rn(v);
        ws3[(size_t)k * 128 + j] = hi;
        ws3[(size_t)(64 + k) * 128 + j] = __float2half_rn(v - __half2float(hi));
        return;
    }
    i -= B;
    if (i < Cc) {
        int k = i >> 8, j = i & 255;
        float v = dW1[k * 128 + (j & 127) + ((j >> 7) ? 64 * 128 : 0)];
        __half hi = __float2half_rn(v);
        wsd[(size_t)k * 256 + j] = hi;
        wsd[(size_t)(64 + k) * 256 + j] = __float2half_rn(v - __half2float(hi));
        return;
    }
    i -= Cc;
    if (i < 128) { bias2[i] = (i >= 64) ? b2[i - 64] : 0.f; return; }
    i -= 128;
    if (i < 128) { bias3[i] = (i >= 64) ? b3[i - 64] : 0.f; return; }
    i -= 128;
    if (i < 256) { biasd[i] = (i < 128) ? db1[i] : 0.f; return; }
}

// ---------------------------------------------------------------------------
// Bucketed CSR fill
// ---------------------------------------------------------------------------
__global__ void fill_kernel(const int* __restrict__ src, const int* __restrict__ dst,
                            const float* __restrict__ ew, int* __restrict__ cursor,
                            int2* __restrict__ csr, int E) {
    int e = blockIdx.x * blockDim.x + threadIdx.x;
    if (e >= E) return;
    int d = dst[e];
    int p = atomicAdd(&cursor[d], 1);
    if (p < CAP) csr[(size_t)d * CAP + p] = make_int2(src[e], __float_as_int(ew[e]));
}

// ---------------------------------------------------------------------------
// Fused layer-1: quad-gather + expand to fp16 (2 -> 128)
// ---------------------------------------------------------------------------
__global__ void layer1_fused(const int2* __restrict__ csr, const int* __restrict__ cnt,
                             const float* __restrict__ x,
                             const float* __restrict__ W1_rel,
                             const float* __restrict__ W1_root,
                             const float* __restrict__ b1,
                             __half* __restrict__ h1, int N) {
    int tid = blockIdx.x * blockDim.x + threadIdx.x;
    int n = tid >> 2;
    int l = tid & 3;
    if (n >= N) return;
    int deg = __ldg(cnt + n);
    const int2* bkt = csr + (size_t)n * CAP;
    float a0 = 0.f, a1 = 0.f;
    for (int i = l; i < deg; i += 4) {
        int2 p = __ldg(bkt + i);
        float w = __int_as_float(p.y);
        float2 xv = __ldg((const float2*)(x + 2 * (size_t)p.x));
        a0 += w * xv.x;
        a1 += w * xv.y;
    }
#pragma unroll
    for (int o = 1; o < 4; o <<= 1) {
        a0 += __shfl_xor_sync(0xFFFFFFFFu, a0, o);
        a1 += __shfl_xor_sync(0xFFFFFFFFu, a1, o);
    }
    float2 xv = __ldg((const float2*)(x + 2 * (size_t)n));
    __half* hp = h1 + (size_t)n * 128;
#pragma unroll 4
    for (int j = 0; j < 16; j++) {
        int f = l * 32 + 2 * j;
        float v0 = a0 * __ldg(W1_rel + f) + a1 * __ldg(W1_rel + 128 + f)
                 + xv.x * __ldg(W1_root + f) + xv.y * __ldg(W1_root + 128 + f) + __ldg(b1 + f);
        float v1 = a0 * __ldg(W1_rel + f + 1) + a1 * __ldg(W1_rel + 129 + f)
                 + xv.x * __ldg(W1_root + f + 1) + xv.y * __ldg(W1_root + 129 + f) + __ldg(b1 + f + 1);
        *(__half2*)(hp + f) = __halves2half2(
            __float2half_rn(fmaxf(v0, 0.f)), __float2half_rn(fmaxf(v1, 0.f)));
    }
}

// ---------------------------------------------------------------------------
// Pipelined wmma GEMM, split weights only.
//   C = H (fp16) @ (W_hi + W_lo) + bias.
//   M-tile 128, N-tile 128, K-tile 32 per step; per step one H tile feeds
//   BOTH W_hi and W_lo tiles (32 wmma/warp between syncs).
// Hs: [NPAD x K] fp16; Ws: [2K x OUT] (hi rows [0,K), lo rows [K,2K)).
// MODE 1: cols [0,64) -> fp16 Cy, cols [64,128) -> fp32 Cr.
// MODE 2: all OUT cols -> fp16 Cy (two-pass smem convert).
// ---------------------------------------------------------------------------
template <int K, int OUT, int MODE>
__global__ __launch_bounds__(256, 2) void gemm_pipe(const __half* __restrict__ Hs,
                                                    const __half* __restrict__ Ws,
                                                    const float* __restrict__ bias,
                                                    __half* __restrict__ Cy,
                                                    float* __restrict__ Cr) {
    constexpr int NKT = K / 32;        // steps
    constexpr int LDH = 40;            // 32 + 8 pad (halves)
    constexpr int LDW = 136;           // 128 + 8 pad
    constexpr int HBh = 128 * LDH;     // halves per H buffer
    constexpr int WBh = 32 * LDW;      // halves per W tile

    extern __shared__ char smem_raw[];
    __half* sh_h   = (__half*)smem_raw;                                  // [2][HBh]
    __half* sh_whi = (__half*)(smem_raw + 2 * HBh * 2);                  // [2][WBh]
    __half* sh_wlo = (__half*)(smem_raw + 2 * HBh * 2 + 2 * WBh * 2);    // [2][WBh]
    float*  sh_b   = (float*)(smem_raw + 2 * HBh * 2 + 4 * WBh * 2);     // 16*128
    float*  sh_c   = (float*)smem_raw;                                   // epilogue reuse

    int m0 = blockIdx.x * 128;
    int n0 = blockIdx.y * 128;
    int t = threadIdx.x;      // 256
    int warp = t >> 5;
    int wm = (warp & 3) * 32;        // 4 m-tiles of 32
    int wn = (warp >> 2) * 64;       // 2 n-tiles of 64

    // bias tile: 16 rows x 128 cols, all rows identical
    {
        int r = t >> 4, c8 = (t & 15) * 8;
        float4 b0 = *(const float4*)(bias + n0 + c8);
        float4 b1 = *(const float4*)(bias + n0 + c8 + 4);
        *(float4*)(sh_b + r * 128 + c8) = b0;
        *(float4*)(sh_b + r * 128 + c8 + 4) = b1;
    }

    auto load_step = [&](int kt, int buf) {
        int kc = kt * 32;
        __half* hb = sh_h + buf * HBh;
        __half* wh = sh_whi + buf * WBh;
        __half* wl = sh_wlo + buf * WBh;
        // H tile: 128 rows x 32 halves = 512 chunks of 16B
#pragma unroll
        for (int i = 0; i < 2; i++) {
            int idx = t + i * 256;
            int row = idx >> 2, ch = idx & 3;
            cp16(hb + row * LDH + ch * 8, Hs + (size_t)(m0 + row) * K + kc + ch * 8);
        }
        // W hi + lo tiles: 32 rows x 128 halves each
#pragma unroll
        for (int i = 0; i < 2; i++) {
            int idx = t + i * 256;
            int row = idx >> 4, ch = idx & 15;
            cp16(wh + row * LDW + ch * 8, Ws + (size_t)(kc + row) * OUT + n0 + ch * 8);
            cp16(wl + row * LDW + ch * 8, Ws + (size_t)(K + kc + row) * OUT + n0 + ch * 8);
        }
    };

    load_step(0, 0);
    cp_commit();

    __syncthreads();  // bias tile visible
    wmma::fragment<wmma::accumulator, 16, 16, 16, float> acc[2][4];
#pragma unroll
    for (int i = 0; i < 2; i++)
#pragma unroll
        for (int j = 0; j < 4; j++)
            wmma::load_matrix_sync(acc[i][j], sh_b + wn + j * 16, 128, wmma::mem_row_major);

    for (int step = 0; step < NKT; step++) {
        int cur = step & 1;
        if (step + 1 < NKT) load_step(step + 1, cur ^ 1);
        cp_commit();
        cp_wait<1>();
        __syncthreads();
        const __half* hb = sh_h + cur * HBh;
        const __half* wh = sh_whi + cur * WBh;
        const __half* wl = sh_wlo + cur * WBh;
#pragma unroll
        for (int kk = 0; kk < 32; kk += 16) {
            wmma::fragment<wmma::matrix_a, 16, 16, 16, __half, wmma::row_major> a0, a1;
            wmma::fragment<wmma::matrix_b, 16, 16, 16, __half, wmma::row_major> b[4];
            wmma::load_matrix_sync(a0, hb + (wm + 0) * LDH + kk, LDH);
            wmma::load_matrix_sync(a1, hb + (wm + 16) * LDH + kk, LDH);
#pragma unroll
            for (int j = 0; j < 4; j++)
                wmma::load_matrix_sync(b[j], wh + kk * LDW + wn + j * 16, LDW);
#pragma unroll
            for (int j = 0; j < 4; j++) {
                wmma::mma_sync(acc[0][j], a0, b[j], acc[0][j]);
                wmma::mma_sync(acc[1][j], a1, b[j], acc[1][j]);
            }
#pragma unroll
            for (int j = 0; j < 4; j++)
                wmma::load_matrix_sync(b[j], wl + kk * LDW + wn + j * 16, LDW);
#pragma unroll
            for (int j = 0; j < 4; j++) {
                wmma::mma_sync(acc[0][j], a0, b[j], acc[0][j]);
                wmma::mma_sync(acc[1][j], a1, b[j], acc[1][j]);
            }
        }
        __syncthreads();
    }

    if constexpr (MODE == 1) {
        // Warps 0-3 (wn==0, cols 0-63 = y): stage in smem, convert to fp16.
        // Warps 4-7 (wn==64, cols 64-127 = r): direct fp32 store (stride 64).
        if (wn == 0) {
#pragma unroll
            for (int i = 0; i < 2; i++)
#pragma unroll
                for (int j = 0; j < 4; j++)
                    wmma::store_matrix_sync(sh_c + (size_t)(wm + i * 16) * 64 + j * 16,
                                            acc[i][j], 64, wmma::mem_row_major);
        } else {
#pragma unroll
            for (int i = 0; i < 2; i++)
#pragma unroll
                for (int j = 0; j < 4; j++)
                    wmma::store_matrix_sync(Cr + (size_t)(m0 + wm + i * 16) * 64 + j * 16,
                                            acc[i][j], 64, wmma::mem_row_major);
        }
        __syncthreads();
        for (int idx = t; idx < 128 * 32; idx += 256) {
            int row = idx >> 5, cp = (idx & 31) * 2;
            float2 v = *(const float2*)(sh_c + (size_t)row * 64 + cp);
            *(__half2*)(Cy + (size_t)(m0 + row) * 64 + cp) =
                __halves2half2(__float2half_rn(v.x), __float2half_rn(v.y));
        }
    } else {
        // MODE 2: all cols fp16, two passes over the two 64-col warp groups
#pragma unroll
        for (int g = 0; g < 2; g++) {
            if ((warp >> 2) == g) {
#pragma unroll
                for (int i = 0; i < 2; i++)
#pragma unroll
                    for (int j = 0; j < 4; j++)
                        wmma::store_matrix_sync(sh_c + (size_t)(wm + i * 16) * 64 + j * 16,
                                                acc[i][j], 64, wmma::mem_row_major);
            }
            __syncthreads();
            for (int idx = t; idx < 128 * 64; idx += 256) {
                int row = idx >> 6, col = idx & 63;
                Cy[(size_t)(m0 + row) * OUT + n0 + g * 64 + col] = __float2half_rn(sh_c[idx]);
            }
            __syncthreads();
        }
    }
}

// ---------------------------------------------------------------------------
// Fused gather + residual + act. y16: fp16 messages [NPAD x 64];
// r32: fp32 residual [NPAD x 64]. 8 lanes/node, lane owns 8 feats.
// Optional fp32 out (z) and/or fp16 out (next gemm input).
// ---------------------------------------------------------------------------
__global__ void gather64(const int2* __restrict__ csr, const int* __restrict__ cnt,
                         const __half* __restrict__ y16, const float* __restrict__ r32,
                         float* __restrict__ out32, __half* __restrict__ out16,
                         int N, int do_relu) {
    int node = blockIdx.x * 32 + (threadIdx.x >> 3);
    int c = threadIdx.x & 7;
    if (node >= N) return;
    int deg = __ldg(cnt + node);
    const int2* bkt = csr + (size_t)node * CAP;
    float4 a0 = make_float4(0, 0, 0, 0);
    float4 a1 = make_float4(0, 0, 0, 0);

    auto accum = [&](int2 p) {
        float w = __int_as_float(p.y);
        uint4 hv = __ldg((const uint4*)(y16 + (size_t)p.x * 64) + c);
        float2 f0 = __half22float2(*(const half2*)&hv.x);
        float2 f1 = __half22float2(*(const half2*)&hv.y);
        float2 f2 = __half22float2(*(const half2*)&hv.z);
        float2 f3 = __half22float2(*(const half2*)&hv.w);
        a0.x += w * f0.x; a0.y += w * f0.y; a0.z += w * f1.x; a0.w += w * f1.y;
        a1.x += w * f2.x; a1.y += w * f2.y; a1.z += w * f3.x; a1.w += w * f3.y;
    };

    int i = 0;
    for (; i + 2 <= deg; i += 2) {
        int2 p0 = __ldg(bkt + i);
        int2 p1 = __ldg(bkt + i + 1);
        accum(p0);
        accum(p1);
    }
    if (i < deg) accum(__ldg(bkt + i));

    const float4* rp = (const float4*)(r32 + (size_t)node * 64);
    float4 rv0 = __ldg(rp + 2 * c);
    float4 rv1 = __ldg(rp + 2 * c + 1);
    a0.x += rv0.x; a0.y += rv0.y; a0.z += rv0.z; a0.w += rv0.w;
    a1.x += rv1.x; a1.y += rv1.y; a1.z += rv1.z; a1.w += rv1.w;
    if (do_relu) {
        a0.x = fmaxf(a0.x, 0.f); a0.y = fmaxf(a0.y, 0.f);
        a0.z = fmaxf(a0.z, 0.f); a0.w = fmaxf(a0.w, 0.f);
        a1.x = fmaxf(a1.x, 0.f); a1.y = fmaxf(a1.y, 0.f);
        a1.z = fmaxf(a1.z, 0.f); a1.w = fmaxf(a1.w, 0.f);
    }
    if (out32) {
        float4* op = (float4*)(out32 + (size_t)node * 64);
        op[2 * c] = a0;
        op[2 * c + 1] = a1;
    }
    if (out16) {
        __half* sp = out16 + (size_t)node * 64;
        int f = 8 * c;
        *(__half2*)(sp + f + 0) = __halves2half2(__float2half_rn(a0.x), __float2half_rn(a0.y));
        *(__half2*)(sp + f + 2) = __halves2half2(__float2half_rn(a0.z), __float2half_rn(a0.w));
        *(__half2*)(sp + f + 4) = __halves2half2(__float2half_rn(a1.x), __float2half_rn(a1.y));
        *(__half2*)(sp + f + 6) = __halves2half2(__float2half_rn(a1.z), __float2half_rn(a1.w));
    }
}

// ---------------------------------------------------------------------------
// Decoder: pred[e] = relu(u[s]+v[d]) . dec_W2 + dec_b2 ; duplicated.
// ---------------------------------------------------------------------------
__global__ void decode_edges_h(const int* __restrict__ src, const int* __restrict__ dst,
                               const __half* __restrict__ uv,
                               const float* __restrict__ W2, const float* __restrict__ b2,
                               float* __restrict__ pred, int OBS) {
    int gt = blockIdx.x * blockDim.x + threadIdx.x;
    int e = gt >> 4;
    int c = gt & 15;
    if (e >= OBS) return;
    int s = src[e];
    int d = dst[e];
    uint4 ub = __ldg((const uint4*)(uv + (size_t)s * 256) + c);
    uint4 vb = __ldg((const uint4*)(uv + (size_t)d * 256 + 128) + c);
    float4 w0 = __ldg((const float4*)W2 + 2 * c);
    float4 w1 = __ldg((const float4*)W2 + 2 * c + 1);

    float2 fu0 = __half22float2(*(const half2*)&ub.x);
    float2 fu1 = __half22float2(*(const half2*)&ub.y);
    float2 fu2 = __half22float2(*(const half2*)&ub.z);
    float2 fu3 = __half22float2(*(const half2*)&ub.w);
    float2 fv0 = __half22float2(*(const half2*)&vb.x);
    float2 fv1 = __half22float2(*(const half2*)&vb.y);
    float2 fv2 = __half22float2(*(const half2*)&vb.z);
    float2 fv3 = __half22float2(*(const half2*)&vb.w);

    float acc = fmaxf(fu0.x + fv0.x, 0.f) * w0.x + fmaxf(fu0.y + fv0.y, 0.f) * w0.y
              + fmaxf(fu1.x + fv1.x, 0.f) * w0.z + fmaxf(fu1.y + fv1.y, 0.f) * w0.w
              + fmaxf(fu2.x + fv2.x, 0.f) * w1.x + fmaxf(fu2.y + fv2.y, 0.f) * w1.y
              + fmaxf(fu3.x + fv3.x, 0.f) * w1.z + fmaxf(fu3.y + fv3.y, 0.f) * w1.w;
#pragma unroll
    for (int o = 8; o > 0; o >>= 1) acc += __shfl_xor_sync(0xFFFFFFFFu, acc, o);
    if (c == 0) {
        float p = acc + __ldg(b2);
        pred[e] = p;
        pred[e + OBS] = p;
    }
}

// ---------------------------------------------------------------------------
// Launch
// ---------------------------------------------------------------------------
extern "C" void kernel_launch(void* const* d_in, const int* in_sizes, int n_in,
                              void* d_out, int out_size) {
    const float* x       = (const float*)d_in[0];
    const int*   ei      = (const int*)d_in[1];
    const float* ew      = (const float*)d_in[2];
    const float* W1_rel  = (const float*)d_in[4];
    const float* b1      = (const float*)d_in[5];
    const float* W1_root = (const float*)d_in[6];
    const float* W2_rel  = (const float*)d_in[7];
    const float* b2      = (const float*)d_in[8];
    const float* W2_root = (const float*)d_in[9];
    const float* W3_rel  = (const float*)d_in[10];
    const float* b3      = (const float*)d_in[11];
    const float* W3_root = (const float*)d_in[12];
    const float* dW1     = (const float*)d_in[13];
    const float* db1     = (const float*)d_in[14];
    const float* dW2     = (const float*)d_in[15];
    const float* db2     = (const float*)d_in[16];

    int N   = in_sizes[0] / 2;
    int E   = in_sizes[2];
    int OBS = E / 2;

    const int* src = ei;
    const int* dst = ei + E;

    float* out = (float*)d_out;
    float* z   = out + 2 * (size_t)OBS;

    float *r32, *bias2, *bias3, *biasd;
    __half *h1, *y16, *h2, *z16, *uv, *ws2, *ws3, *wsd;
    int *cursor;
    int2* csr;
    cudaGetSymbolAddress((void**)&h1,     g_h1);
    cudaGetSymbolAddress((void**)&y16,    g_y16);
    cudaGetSymbolAddress((void**)&r32,    g_r32);
    cudaGetSymbolAddress((void**)&h2,     g_h2);
    cudaGetSymbolAddress((void**)&z16,    g_z16);
    cudaGetSymbolAddress((void**)&uv,     g_uv);
    cudaGetSymbolAddress((void**)&ws2,    g_ws2);
    cudaGetSymbolAddress((void**)&ws3,    g_ws3);
    cudaGetSymbolAddress((void**)&wsd,    g_wsd);
    cudaGetSymbolAddress((void**)&bias2,  g_bias2);
    cudaGetSymbolAddress((void**)&bias3,  g_bias3);
    cudaGetSymbolAddress((void**)&biasd,  g_biasd);
    cudaGetSymbolAddress((void**)&cursor, g_cursor);
    cudaGetSymbolAddress((void**)&csr,    g_csr);

    // dyn smem: 2 H bufs + 2x2 W bufs + bias tile
    const int SMEM = 2 * (128 * 40) * 2 + 4 * (32 * 136) * 2 + 16 * 128 * 4;  // 63488
    cudaFuncSetAttribute(gemm_pipe<128, 128, 1>,
                         cudaFuncAttributeMaxDynamicSharedMemorySize, SMEM);
    cudaFuncSetAttribute(gemm_pipe<64, 128, 1>,
                         cudaFuncAttributeMaxDynamicSharedMemorySize, SMEM);
    cudaFuncSetAttribute(gemm_pipe<64, 256, 2>,
                         cudaFuncAttributeMaxDynamicSharedMemorySize, SMEM);

    const int TB = 256;
    int eb = (E + TB - 1) / TB;
    int mb128 = (N + 127) / 128;

    // ---- prep (1 launch) ----
    {
        int total = 128 * 128 + 64 * 128 + 64 * 256 + 128 + 128 + 256;
        prep_all<<<(total + TB - 1) / TB, TB>>>(W2_rel, W2_root, W3_rel, W3_root, dW1,
                                                b2, b3, db1, ws2, ws3, wsd,
                                                bias2, bias3, biasd);
    }

    // ---- Bucketed CSR ----
    cudaMemsetAsync(cursor, 0, (size_t)N * sizeof(int));
    fill_kernel<<<eb, TB>>>(src, dst, ew, cursor, csr, E);

    // ---- Layer 1 fused ----
    layer1_fused<<<(N * 4 + TB - 1) / TB, TB>>>(csr, cursor, x, W1_rel, W1_root, b1, h1, N);

    // ---- Layer 2: gemm (y fp16 | r fp32) + fused gather ----
    gemm_pipe<128, 128, 1><<<dim3(mb128, 1), 256, SMEM>>>(h1, ws2, bias2, y16, r32);
    gather64<<<(N + 31) / 32, TB>>>(csr, cursor, y16, r32, nullptr, h2, N, 1);

    // ---- Layer 3 ----
    gemm_pipe<64, 128, 1><<<dim3(mb128, 1), 256, SMEM>>>(h2, ws3, bias3, y16, r32);
    gather64<<<(N + 31) / 32, TB>>>(csr, cursor, y16, r32, z, z16, N, 0);

    // ---- Decoder ----
    gemm_pipe<64, 256, 2><<<dim3(mb128, 2), 256, SMEM>>>(z16, wsd, biasd, uv, nullptr);
    decode_edges_h<<<((size_t)OBS * 16 + TB - 1) / TB, TB>>>(src, dst, uv, dW2, db2, out, OBS);
}